// round 5
// baseline (speedup 1.0000x reference)
#include <cuda_runtime.h>
#include <cuda_bf16.h>
#include <cstdint>

#define LEAKY 0.01f

static constexpr int MAX_N = 100000;
static constexpr int MAX_E = 1600000;

// Scratch (module-scope device globals; allocation inside kernel_launch is forbidden)
__device__ float g_h[(size_t)MAX_N * 128];    // GEMM output / gather source
__device__ float g_agg[(size_t)MAX_N * 128];  // gather destination / next GEMM input
__device__ float g_rs_out[MAX_N];             // rsqrt(max(out_deg,1))
__device__ float g_rs_in[MAX_N];              // rsqrt(max(in_deg,1))
__device__ int   g_indeg[MAX_N];              // int in-degree counts
__device__ int   g_excl[MAX_N];               // scan scratch
__device__ int   g_row_start[MAX_N + 1];      // CSR row offsets (by dst)
__device__ int   g_cursor[MAX_N];             // CSR fill cursors
__device__ int   g_csr_src[MAX_E];            // CSR column (src node) array
__device__ int   g_bsum[512];                 // scan block sums
__device__ uint2 g_bt[128 * 128];             // W^T tf32 (hi,lo) interleaved [n][k]

__device__ __forceinline__ float lrelu(float t) {
    return (t >= 0.f) ? t : LEAKY * t;
}

__device__ __forceinline__ uint32_t f2tf32(float x) {
    uint32_t r;
    asm("cvt.rna.tf32.f32 %0, %1;" : "=r"(r) : "f"(x));
    return r;
}

__device__ __forceinline__ void mma_tf32(float* d, const uint32_t* a, const uint32_t* b) {
    asm volatile(
        "mma.sync.aligned.m16n8k8.row.col.f32.tf32.tf32.f32 "
        "{%0,%1,%2,%3}, {%4,%5,%6,%7}, {%8,%9}, {%0,%1,%2,%3};"
        : "+f"(d[0]), "+f"(d[1]), "+f"(d[2]), "+f"(d[3])
        : "r"(a[0]), "r"(a[1]), "r"(a[2]), "r"(a[3]), "r"(b[0]), "r"(b[1]));
}

// ---------------------------------------------------------------------------
// Degrees (split: out-degree chain feeds gemm0; in-degree chain feeds CSR)
// ---------------------------------------------------------------------------
__global__ void outdeg_kernel(const int* __restrict__ src, float* __restrict__ dout, int E) {
    int i = blockIdx.x * blockDim.x + threadIdx.x;
    if (i < E) atomicAdd(&dout[src[i]], 1.0f);
}

__global__ void indeg_kernel(const int* __restrict__ dst, int* __restrict__ indeg, int E) {
    int i = blockIdx.x * blockDim.x + threadIdx.x;
    if (i < E) atomicAdd(&indeg[dst[i]], 1);
}

__global__ void rsqrt_out_kernel(float* __restrict__ dout, int N) {
    int i = blockIdx.x * blockDim.x + threadIdx.x;
    if (i < N) dout[i] = rsqrtf(fmaxf(dout[i], 1.0f));
}

__global__ void rsqrt_in_kernel(const int* __restrict__ indeg, float* __restrict__ rsin, int N) {
    int i = blockIdx.x * blockDim.x + threadIdx.x;
    if (i < N) rsin[i] = rsqrtf(fmaxf((float)indeg[i], 1.0f));
}

// ---------------------------------------------------------------------------
// Exclusive scan over in-degrees
// ---------------------------------------------------------------------------
__global__ void scan_block(const int* __restrict__ deg, int* __restrict__ excl,
                           int* __restrict__ bsum, int N) {
    __shared__ int ts[256];
    int tid = threadIdx.x;
    int base = blockIdx.x * 1024 + tid * 4;
    int v[4];
    int sum = 0;
#pragma unroll
    for (int i = 0; i < 4; i++) {
        int idx = base + i;
        v[i] = (idx < N) ? deg[idx] : 0;
        sum += v[i];
    }
    ts[tid] = sum;
    __syncthreads();
    for (int off = 1; off < 256; off <<= 1) {
        int t = (tid >= off) ? ts[tid - off] : 0;
        __syncthreads();
        ts[tid] += t;
        __syncthreads();
    }
    if (tid == 255) bsum[blockIdx.x] = ts[255];
    int run = ts[tid] - sum;
#pragma unroll
    for (int i = 0; i < 4; i++) {
        int idx = base + i;
        if (idx < N) excl[idx] = run;
        run += v[i];
    }
}

__global__ void scan_bsum(int* __restrict__ bsum, int nb) {
    __shared__ int s[512];
    int tid = threadIdx.x;
    int v = (tid < nb) ? bsum[tid] : 0;
    s[tid] = v;
    __syncthreads();
    for (int off = 1; off < 512; off <<= 1) {
        int t = (tid >= off) ? s[tid - off] : 0;
        __syncthreads();
        s[tid] += t;
        __syncthreads();
    }
    if (tid < nb) bsum[tid] = s[tid] - v;
}

__global__ void scan_add(const int* __restrict__ excl, const int* __restrict__ bsum,
                         int* __restrict__ row_start, int* __restrict__ cursor,
                         int N, int E) {
    int i = blockIdx.x * blockDim.x + threadIdx.x;
    if (i < N) {
        int v = excl[i] + bsum[i >> 10];
        row_start[i] = v;
        cursor[i] = v;
    }
    if (i == 0) row_start[N] = E;
}

__global__ void fill_csr(const int* __restrict__ src, const int* __restrict__ dst,
                         int* __restrict__ cursor, int* __restrict__ csr_src, int E) {
    int e = blockIdx.x * blockDim.x + threadIdx.x;
    if (e < E) {
        int pos = atomicAdd(&cursor[dst[e]], 1);
        csr_src[pos] = src[e];
    }
}

// ---------------------------------------------------------------------------
// W split: Bt[n*K + k] = (tf32_hi, tf32_lo) of W[k*BN + n]  (transpose+convert)
// ---------------------------------------------------------------------------
__global__ void split_w(const float* __restrict__ W, uint2* __restrict__ bt, int K, int BN) {
    int idx = blockIdx.x * blockDim.x + threadIdx.x;
    if (idx >= K * BN) return;
    int k = idx / BN;
    int n = idx % BN;
    float w = W[idx];
    uint32_t hi = f2tf32(w);
    uint32_t lo = f2tf32(w - __uint_as_float(hi));
    bt[n * K + k] = make_uint2(hi, lo);
}

// ---------------------------------------------------------------------------
// TF32 mma.sync GEMM (3xTF32 split): out[N,BN] = pre(A)[N,K] @ W[K,BN]
//   FIRST=true :  pre(a) = a * rs_out[row]
//   FIRST=false:  pre(a) = lrelu(a * rs_in[row] + bprev[k]) * rs_out[row]
// SMEM elements are uint2(hi,lo); row stride 36 uint2 (72 words ≡ 8 mod 32:
// conflict-free fragment loads). 256 threads, BM=128, full BN, BK=32 chunks.
// ---------------------------------------------------------------------------
template<int K, int BN, bool FIRST>
__global__ __launch_bounds__(256)
void gemm_mma(const float* __restrict__ A, const uint2* __restrict__ Bt,
              const float* __restrict__ bprev,
              const float* __restrict__ rs_out, const float* __restrict__ rs_in,
              float* __restrict__ out, int nrows)
{
    constexpr int WARPS_M = (BN == 128) ? 2 : 4;
    constexpr int WARPS_N = 8 / WARPS_M;
    constexpr int WM = 128 / WARPS_M;   // 64 or 32
    constexpr int WN = BN / WARPS_N;    // 32
    constexpr int MF = WM / 16;         // 4 or 2
    constexpr int NF = WN / 8;          // 4
    constexpr int S2 = 36;              // uint2 stride per row

    extern __shared__ __align__(16) uint2 smem2[];
    uint2* As = smem2;            // [128][36]
    uint2* Bs = smem2 + 128 * S2; // [BN][36]

    const int tid = threadIdx.x;
    const int wid = tid >> 5;
    const int lane = tid & 31;
    const int wm = wid % WARPS_M;
    const int wn = wid / WARPS_M;
    const int rowBase = blockIdx.x * 128;
    const int g = lane >> 2;
    const int t4 = lane & 3;

    float acc[MF][NF][4];
#pragma unroll
    for (int i = 0; i < MF; i++)
#pragma unroll
        for (int j = 0; j < NF; j++)
#pragma unroll
            for (int c = 0; c < 4; c++) acc[i][j][c] = 0.f;

    for (int k0 = 0; k0 < K; k0 += 32) {
        // ---- A tile: 1024 float4 slots, 4/thread, fused epilogue + tf32 split ----
#pragma unroll
        for (int i = 0; i < 4; i++) {
            int lin = tid + i * 256;
            int r = lin >> 3;
            int kq = lin & 7;
            int row = rowBase + r;
            float4 v = make_float4(0.f, 0.f, 0.f, 0.f);
            if (row < nrows) {
                v = *(const float4*)(A + (size_t)row * K + k0 + kq * 4);
                if (FIRST) {
                    float ro = rs_out[row];
                    v.x *= ro; v.y *= ro; v.z *= ro; v.w *= ro;
                } else {
                    float ri = rs_in[row];
                    float ro = rs_out[row];
                    int kk = k0 + kq * 4;
                    v.x = lrelu(fmaf(v.x, ri, bprev[kk + 0])) * ro;
                    v.y = lrelu(fmaf(v.y, ri, bprev[kk + 1])) * ro;
                    v.z = lrelu(fmaf(v.z, ri, bprev[kk + 2])) * ro;
                    v.w = lrelu(fmaf(v.w, ri, bprev[kk + 3])) * ro;
                }
            }
            uint4 w0, w1;
            w0.x = f2tf32(v.x); w0.y = f2tf32(v.x - __uint_as_float(w0.x));
            w0.z = f2tf32(v.y); w0.w = f2tf32(v.y - __uint_as_float(w0.z));
            w1.x = f2tf32(v.z); w1.y = f2tf32(v.z - __uint_as_float(w1.x));
            w1.z = f2tf32(v.w); w1.w = f2tf32(v.w - __uint_as_float(w1.z));
            *(uint4*)(As + r * S2 + kq * 4)     = w0;
            *(uint4*)(As + r * S2 + kq * 4 + 2) = w1;
        }
        // ---- B tile: interleaved global -> SMEM copy (uint4 = 2 elements) ----
        constexpr int BSLOTS = BN * 16;   // uint4 slots per chunk
        constexpr int BPER = BSLOTS / 256;
#pragma unroll
        for (int i = 0; i < BPER; i++) {
            int lin = tid + i * 256;
            int n = lin >> 4;
            int q = lin & 15;
            uint4 v = *(const uint4*)(Bt + (size_t)n * K + k0 + q * 2);
            *(uint4*)(Bs + n * S2 + q * 2) = v;
        }
        __syncthreads();

        // ---- compute: 4 k-steps of 8 ----
#pragma unroll
        for (int ks = 0; ks < 4; ks++) {
            const int kk = ks * 8;
            uint32_t ah[MF][4], al[MF][4];
#pragma unroll
            for (int mf = 0; mf < MF; mf++) {
                int r = wm * WM + mf * 16 + g;
                int c = kk + t4;
                uint2 v0 = As[r * S2 + c];
                uint2 v1 = As[(r + 8) * S2 + c];
                uint2 v2 = As[r * S2 + c + 4];
                uint2 v3 = As[(r + 8) * S2 + c + 4];
                ah[mf][0] = v0.x; al[mf][0] = v0.y;
                ah[mf][1] = v1.x; al[mf][1] = v1.y;
                ah[mf][2] = v2.x; al[mf][2] = v2.y;
                ah[mf][3] = v3.x; al[mf][3] = v3.y;
            }
            uint32_t bh[NF][2], bl[NF][2];
#pragma unroll
            for (int nf = 0; nf < NF; nf++) {
                int n = wn * WN + nf * 8 + g;
                uint2 u0 = Bs[n * S2 + kk + t4];
                uint2 u1 = Bs[n * S2 + kk + t4 + 4];
                bh[nf][0] = u0.x; bl[nf][0] = u0.y;
                bh[nf][1] = u1.x; bl[nf][1] = u1.y;
            }
#pragma unroll
            for (int mf = 0; mf < MF; mf++)
#pragma unroll
                for (int nf = 0; nf < NF; nf++) {
                    mma_tf32(acc[mf][nf], ah[mf], bh[nf]);
                    mma_tf32(acc[mf][nf], al[mf], bh[nf]);
                    mma_tf32(acc[mf][nf], ah[mf], bl[nf]);
                }
        }
        __syncthreads();
    }

    // ---- store ----
#pragma unroll
    for (int mf = 0; mf < MF; mf++) {
#pragma unroll
        for (int nf = 0; nf < NF; nf++) {
            int r0 = rowBase + wm * WM + mf * 16 + g;
            int col = wn * WN + nf * 8 + t4 * 2;
            if (r0 < nrows)
                *(float2*)(out + (size_t)r0 * BN + col) =
                    make_float2(acc[mf][nf][0], acc[mf][nf][1]);
            if (r0 + 8 < nrows)
                *(float2*)(out + (size_t)(r0 + 8) * BN + col) =
                    make_float2(acc[mf][nf][2], acc[mf][nf][3]);
        }
    }
}

// ---------------------------------------------------------------------------
// CSR gather aggregation (unrolled x4 for MLP)
// ---------------------------------------------------------------------------
__global__ __launch_bounds__(256)
void gather128(const int* __restrict__ row_start, const int* __restrict__ csr,
               const float* __restrict__ h, float* __restrict__ agg, int N)
{
    int warp = (blockIdx.x * blockDim.x + threadIdx.x) >> 5;
    int lane = threadIdx.x & 31;
    if (warp >= N) return;
    int start = row_start[warp];
    int end   = row_start[warp + 1];
    float4 acc = make_float4(0.f, 0.f, 0.f, 0.f);
    int j = start;
    for (; j + 3 < end; j += 4) {
        int s0 = __ldg(&csr[j]);
        int s1 = __ldg(&csr[j + 1]);
        int s2 = __ldg(&csr[j + 2]);
        int s3 = __ldg(&csr[j + 3]);
        float4 v0 = *(const float4*)(h + (size_t)s0 * 128 + lane * 4);
        float4 v1 = *(const float4*)(h + (size_t)s1 * 128 + lane * 4);
        float4 v2 = *(const float4*)(h + (size_t)s2 * 128 + lane * 4);
        float4 v3 = *(const float4*)(h + (size_t)s3 * 128 + lane * 4);
        acc.x += (v0.x + v1.x) + (v2.x + v3.x);
        acc.y += (v0.y + v1.y) + (v2.y + v3.y);
        acc.z += (v0.z + v1.z) + (v2.z + v3.z);
        acc.w += (v0.w + v1.w) + (v2.w + v3.w);
    }
    for (; j < end; j++) {
        int s0 = __ldg(&csr[j]);
        float4 v0 = *(const float4*)(h + (size_t)s0 * 128 + lane * 4);
        acc.x += v0.x; acc.y += v0.y; acc.z += v0.z; acc.w += v0.w;
    }
    *(float4*)(agg + (size_t)warp * 128 + lane * 4) = acc;
}

__global__ __launch_bounds__(256)
void gather64(const int* __restrict__ row_start, const int* __restrict__ csr,
              const float* __restrict__ h, float* __restrict__ agg, int N)
{
    int warp = (blockIdx.x * blockDim.x + threadIdx.x) >> 5;
    int lane = threadIdx.x & 31;
    if (warp >= N) return;
    int start = row_start[warp];
    int end   = row_start[warp + 1];
    float2 acc = make_float2(0.f, 0.f);
    int j = start;
    for (; j + 3 < end; j += 4) {
        int s0 = __ldg(&csr[j]);
        int s1 = __ldg(&csr[j + 1]);
        int s2 = __ldg(&csr[j + 2]);
        int s3 = __ldg(&csr[j + 3]);
        float2 v0 = *(const float2*)(h + (size_t)s0 * 64 + lane * 2);
        float2 v1 = *(const float2*)(h + (size_t)s1 * 64 + lane * 2);
        float2 v2 = *(const float2*)(h + (size_t)s2 * 64 + lane * 2);
        float2 v3 = *(const float2*)(h + (size_t)s3 * 64 + lane * 2);
        acc.x += (v0.x + v1.x) + (v2.x + v3.x);
        acc.y += (v0.y + v1.y) + (v2.y + v3.y);
    }
    for (; j < end; j++) {
        int s0 = __ldg(&csr[j]);
        float2 v0 = *(const float2*)(h + (size_t)s0 * 64 + lane * 2);
        acc.x += v0.x; acc.y += v0.y;
    }
    *(float2*)(agg + (size_t)warp * 64 + lane * 2) = acc;
}

// Final-layer gather with fused epilogue: out = lrelu(acc * rs_in + b2)
__global__ __launch_bounds__(256)
void gather64_epi(const int* __restrict__ row_start, const int* __restrict__ csr,
                  const float* __restrict__ h, const float* __restrict__ rs_in,
                  const float* __restrict__ b, float* __restrict__ out, int N)
{
    int warp = (blockIdx.x * blockDim.x + threadIdx.x) >> 5;
    int lane = threadIdx.x & 31;
    if (warp >= N) return;
    int start = row_start[warp];
    int end   = row_start[warp + 1];
    float2 acc = make_float2(0.f, 0.f);
    int j = start;
    for (; j + 3 < end; j += 4) {
        int s0 = __ldg(&csr[j]);
        int s1 = __ldg(&csr[j + 1]);
        int s2 = __ldg(&csr[j + 2]);
        int s3 = __ldg(&csr[j + 3]);
        float2 v0 = *(const float2*)(h + (size_t)s0 * 64 + lane * 2);
        float2 v1 = *(const float2*)(h + (size_t)s1 * 64 + lane * 2);
        float2 v2 = *(const float2*)(h + (size_t)s2 * 64 + lane * 2);
        float2 v3 = *(const float2*)(h + (size_t)s3 * 64 + lane * 2);
        acc.x += (v0.x + v1.x) + (v2.x + v3.x);
        acc.y += (v0.y + v1.y) + (v2.y + v3.y);
    }
    for (; j < end; j++) {
        int s0 = __ldg(&csr[j]);
        float2 v0 = *(const float2*)(h + (size_t)s0 * 64 + lane * 2);
        acc.x += v0.x; acc.y += v0.y;
    }
    float ri = rs_in[warp];
    int c = lane * 2;
    float2 o;
    o.x = lrelu(fmaf(acc.x, ri, b[c + 0]));
    o.y = lrelu(fmaf(acc.y, ri, b[c + 1]));
    *(float2*)(out + (size_t)warp * 64 + c) = o;
}

// ---------------------------------------------------------------------------
// Launch
// ---------------------------------------------------------------------------
static inline int cdiv(int a, int b) { return (a + b - 1) / b; }

extern "C" void kernel_launch(void* const* d_in, const int* in_sizes, int n_in,
                              void* d_out, int out_size)
{
    const float* n_feat = (const float*)d_in[0];
    const int*   src    = (const int*)  d_in[1];
    const int*   dst    = (const int*)  d_in[2];
    const float* W0     = (const float*)d_in[3];
    const float* b0     = (const float*)d_in[4];
    const float* W1     = (const float*)d_in[5];
    const float* b1     = (const float*)d_in[6];
    const float* W2     = (const float*)d_in[7];
    const float* b2     = (const float*)d_in[8];
    float* out = (float*)d_out;

    const int N = in_sizes[0] / 128;
    const int E = in_sizes[1];

    float *d_h, *d_agg, *d_rso, *d_rsi;
    int *d_indeg, *d_excl, *d_rs, *d_cur, *d_csr, *d_bsum;
    uint2 *d_bt;
    cudaGetSymbolAddress((void**)&d_h,    g_h);
    cudaGetSymbolAddress((void**)&d_agg,  g_agg);
    cudaGetSymbolAddress((void**)&d_rso,  g_rs_out);
    cudaGetSymbolAddress((void**)&d_rsi,  g_rs_in);
    cudaGetSymbolAddress((void**)&d_indeg, g_indeg);
    cudaGetSymbolAddress((void**)&d_excl, g_excl);
    cudaGetSymbolAddress((void**)&d_rs,   g_row_start);
    cudaGetSymbolAddress((void**)&d_cur,  g_cursor);
    cudaGetSymbolAddress((void**)&d_csr,  g_csr_src);
    cudaGetSymbolAddress((void**)&d_bsum, g_bsum);
    cudaGetSymbolAddress((void**)&d_bt,   g_bt);

    constexpr int SMEM_128 = (128 + 128) * 36 * 8;  // 73728
    constexpr int SMEM_64  = (128 + 64) * 36 * 8;   // 55296

    // One-time setup on the (uncaptured) correctness call
    static cudaStream_t s2 = nullptr;
    static cudaEvent_t ev0 = nullptr, ev1 = nullptr;
    if (!s2) {
        cudaFuncSetAttribute(gemm_mma<128, 128, true>,
                             cudaFuncAttributeMaxDynamicSharedMemorySize, SMEM_128);
        cudaFuncSetAttribute(gemm_mma<128, 64, false>,
                             cudaFuncAttributeMaxDynamicSharedMemorySize, SMEM_64);
        cudaFuncSetAttribute(gemm_mma<64, 64, false>,
                             cudaFuncAttributeMaxDynamicSharedMemorySize, SMEM_64);
        cudaStreamCreateWithFlags(&s2, cudaStreamNonBlocking);
        cudaEventCreateWithFlags(&ev0, cudaEventDisableTiming);
        cudaEventCreateWithFlags(&ev1, cudaEventDisableTiming);
    }

    // ---- fork: CSR/in-degree chain on s2, out-degree+gemm0 chain on main ----
    cudaEventRecord(ev0, 0);
    cudaStreamWaitEvent(s2, ev0, 0);

    // s2: in-degree -> rs_in -> scan -> fill_csr
    cudaMemsetAsync(d_indeg, 0, (size_t)N * sizeof(int), s2);
    indeg_kernel<<<cdiv(E, 256), 256, 0, s2>>>(dst, d_indeg, E);
    rsqrt_in_kernel<<<cdiv(N, 256), 256, 0, s2>>>(d_indeg, d_rsi, N);
    const int nb = cdiv(N, 1024);
    scan_block<<<nb, 256, 0, s2>>>(d_indeg, d_excl, d_bsum, N);
    scan_bsum<<<1, 512, 0, s2>>>(d_bsum, nb);
    scan_add<<<cdiv(N, 256), 256, 0, s2>>>(d_excl, d_bsum, d_rs, d_cur, N, E);
    fill_csr<<<cdiv(E, 256), 256, 0, s2>>>(src, dst, d_cur, d_csr, E);
    cudaEventRecord(ev1, s2);

    // main: out-degree -> rs_out -> split W0 -> gemm0
    cudaMemsetAsync(d_rso, 0, (size_t)N * sizeof(float));
    outdeg_kernel<<<cdiv(E, 256), 256>>>(src, d_rso, E);
    rsqrt_out_kernel<<<cdiv(N, 256), 256>>>(d_rso, N);
    split_w<<<cdiv(128 * 128, 256), 256>>>(W0, d_bt, 128, 128);

    const int gemm_blocks = cdiv(N, 128);
    const int gw_blocks = cdiv(N, 8);

    gemm_mma<128, 128, true><<<gemm_blocks, 256, SMEM_128>>>(
        n_feat, d_bt, nullptr, d_rso, d_rsi, d_h, N);

    // ---- join: gathers need the CSR ----
    cudaStreamWaitEvent(0, ev1, 0);
    gather128<<<gw_blocks, 256>>>(d_rs, d_csr, d_h, d_agg, N);

    // --- layer 1: 128 -> 64 ---
    split_w<<<cdiv(128 * 64, 256), 256>>>(W1, d_bt, 128, 64);
    gemm_mma<128, 64, false><<<gemm_blocks, 256, SMEM_64>>>(
        d_agg, d_bt, b0, d_rso, d_rsi, d_h, N);
    gather64<<<gw_blocks, 256>>>(d_rs, d_csr, d_h, d_agg, N);

    // --- layer 2: 64 -> 64 ---
    split_w<<<cdiv(64 * 64, 256), 256>>>(W2, d_bt, 64, 64);
    gemm_mma<64, 64, false><<<gemm_blocks, 256, SMEM_64>>>(
        d_agg, d_bt, b1, d_rso, d_rsi, d_h, N);
    gather64_epi<<<gw_blocks, 256>>>(d_rs, d_csr, d_h, d_rsi, b2, out, N);
}

// round 6
// speedup vs baseline: 1.0139x; 1.0139x over previous
#include <cuda_runtime.h>
#include <cuda_bf16.h>
#include <cstdint>

#define LEAKY 0.01f

static constexpr int MAX_N = 100000;
static constexpr int MAX_E = 1600000;

// Scratch (module-scope device globals; allocation inside kernel_launch is forbidden)
__device__ float g_h[(size_t)MAX_N * 128];    // GEMM output / gather source
__device__ float g_agg[(size_t)MAX_N * 128];  // gather destination / next GEMM input
__device__ float g_rs_out[MAX_N];             // rsqrt(max(out_deg,1))
__device__ float g_rs_in[MAX_N];              // rsqrt(max(in_deg,1))
__device__ int   g_indeg[MAX_N];              // int in-degree counts
__device__ int   g_excl[MAX_N];               // scan scratch
__device__ int   g_row_start[MAX_N + 1];      // CSR row offsets (by dst)
__device__ int   g_cursor[MAX_N];             // CSR fill cursors
__device__ int   g_csr_src[MAX_E];            // CSR column (src node) array
__device__ int   g_bsum[512];                 // scan block sums
__device__ uint2 g_bt[128 * 128];             // W^T tf32 (hi,lo) interleaved [n][k]

__device__ __forceinline__ float lrelu(float t) {
    return (t >= 0.f) ? t : LEAKY * t;
}

__device__ __forceinline__ uint32_t f2tf32(float x) {
    uint32_t r;
    asm("cvt.rna.tf32.f32 %0, %1;" : "=r"(r) : "f"(x));
    return r;
}

__device__ __forceinline__ void mma_tf32(float* d, const uint32_t* a, const uint32_t* b) {
    asm volatile(
        "mma.sync.aligned.m16n8k8.row.col.f32.tf32.tf32.f32 "
        "{%0,%1,%2,%3}, {%4,%5,%6,%7}, {%8,%9}, {%0,%1,%2,%3};"
        : "+f"(d[0]), "+f"(d[1]), "+f"(d[2]), "+f"(d[3])
        : "r"(a[0]), "r"(a[1]), "r"(a[2]), "r"(a[3]), "r"(b[0]), "r"(b[1]));
}

// ---------------------------------------------------------------------------
// Degrees: single E pass, both atomics
// ---------------------------------------------------------------------------
__global__ void deg_kernel(const int* __restrict__ src, const int* __restrict__ dst,
                           float* __restrict__ dout, int* __restrict__ indeg, int E) {
    int i = blockIdx.x * blockDim.x + threadIdx.x;
    if (i < E) {
        atomicAdd(&dout[src[i]], 1.0f);
        atomicAdd(&indeg[dst[i]], 1);
    }
}

__global__ void rsqrt_kernel(float* __restrict__ dout, const int* __restrict__ indeg,
                             float* __restrict__ rsin, int N) {
    int i = blockIdx.x * blockDim.x + threadIdx.x;
    if (i < N) {
        dout[i] = rsqrtf(fmaxf(dout[i], 1.0f));
        rsin[i] = rsqrtf(fmaxf((float)indeg[i], 1.0f));
    }
}

// ---------------------------------------------------------------------------
// Exclusive scan over in-degrees
// ---------------------------------------------------------------------------
__global__ void scan_block(const int* __restrict__ deg, int* __restrict__ excl,
                           int* __restrict__ bsum, int N) {
    __shared__ int ts[256];
    int tid = threadIdx.x;
    int base = blockIdx.x * 1024 + tid * 4;
    int v[4];
    int sum = 0;
#pragma unroll
    for (int i = 0; i < 4; i++) {
        int idx = base + i;
        v[i] = (idx < N) ? deg[idx] : 0;
        sum += v[i];
    }
    ts[tid] = sum;
    __syncthreads();
    for (int off = 1; off < 256; off <<= 1) {
        int t = (tid >= off) ? ts[tid - off] : 0;
        __syncthreads();
        ts[tid] += t;
        __syncthreads();
    }
    if (tid == 255) bsum[blockIdx.x] = ts[255];
    int run = ts[tid] - sum;
#pragma unroll
    for (int i = 0; i < 4; i++) {
        int idx = base + i;
        if (idx < N) excl[idx] = run;
        run += v[i];
    }
}

__global__ void scan_bsum(int* __restrict__ bsum, int nb) {
    __shared__ int s[512];
    int tid = threadIdx.x;
    int v = (tid < nb) ? bsum[tid] : 0;
    s[tid] = v;
    __syncthreads();
    for (int off = 1; off < 512; off <<= 1) {
        int t = (tid >= off) ? s[tid - off] : 0;
        __syncthreads();
        s[tid] += t;
        __syncthreads();
    }
    if (tid < nb) bsum[tid] = s[tid] - v;
}

__global__ void scan_add(const int* __restrict__ excl, const int* __restrict__ bsum,
                         int* __restrict__ row_start, int* __restrict__ cursor,
                         int N, int E) {
    int i = blockIdx.x * blockDim.x + threadIdx.x;
    if (i < N) {
        int v = excl[i] + bsum[i >> 10];
        row_start[i] = v;
        cursor[i] = v;
    }
    if (i == 0) row_start[N] = E;
}

__global__ void fill_csr(const int* __restrict__ src, const int* __restrict__ dst,
                         int* __restrict__ cursor, int* __restrict__ csr_src, int E) {
    int e = blockIdx.x * blockDim.x + threadIdx.x;
    if (e < E) {
        int pos = atomicAdd(&cursor[dst[e]], 1);
        csr_src[pos] = src[e];
    }
}

// ---------------------------------------------------------------------------
// W split: Bt[n*K + k] = (tf32_hi, tf32_lo) of W[k*BN + n]  (transpose+convert)
// ---------------------------------------------------------------------------
__global__ void split_w(const float* __restrict__ W, uint2* __restrict__ bt, int K, int BN) {
    int idx = blockIdx.x * blockDim.x + threadIdx.x;
    if (idx >= K * BN) return;
    int k = idx / BN;
    int n = idx % BN;
    float w = W[idx];
    uint32_t hi = f2tf32(w);
    uint32_t lo = f2tf32(w - __uint_as_float(hi));
    bt[n * K + k] = make_uint2(hi, lo);
}

// ---------------------------------------------------------------------------
// TF32 mma.sync GEMM (3xTF32 split): out[N,BN] = pre(A)[N,K] @ W[K,BN]
//   FIRST=true :  pre(a) = a * rs_out[row]
//   FIRST=false:  pre(a) = lrelu(a * rs_in[row] + bprev[k]) * rs_out[row]
// SMEM elements are uint2(hi,lo); row stride 36 uint2. 256 threads, BM=128,
// full BN, BK=32 chunks.
// ---------------------------------------------------------------------------
template<int K, int BN, bool FIRST>
__global__ __launch_bounds__(256)
void gemm_mma(const float* __restrict__ A, const uint2* __restrict__ Bt,
              const float* __restrict__ bprev,
              const float* __restrict__ rs_out, const float* __restrict__ rs_in,
              float* __restrict__ out, int nrows)
{
    constexpr int WARPS_M = (BN == 128) ? 2 : 4;
    constexpr int WARPS_N = 8 / WARPS_M;
    constexpr int WM = 128 / WARPS_M;   // 64 or 32
    constexpr int WN = BN / WARPS_N;    // 32
    constexpr int MF = WM / 16;         // 4 or 2
    constexpr int NF = WN / 8;          // 4
    constexpr int S2 = 36;              // uint2 stride per row

    extern __shared__ __align__(16) uint2 smem2[];
    uint2* As = smem2;            // [128][36]
    uint2* Bs = smem2 + 128 * S2; // [BN][36]

    const int tid = threadIdx.x;
    const int wid = tid >> 5;
    const int lane = tid & 31;
    const int wm = wid % WARPS_M;
    const int wn = wid / WARPS_M;
    const int rowBase = blockIdx.x * 128;
    const int g = lane >> 2;
    const int t4 = lane & 3;

    float acc[MF][NF][4];
#pragma unroll
    for (int i = 0; i < MF; i++)
#pragma unroll
        for (int j = 0; j < NF; j++)
#pragma unroll
            for (int c = 0; c < 4; c++) acc[i][j][c] = 0.f;

    for (int k0 = 0; k0 < K; k0 += 32) {
        // ---- A tile: 1024 float4 slots, 4/thread, fused epilogue + tf32 split ----
#pragma unroll
        for (int i = 0; i < 4; i++) {
            int lin = tid + i * 256;
            int r = lin >> 3;
            int kq = lin & 7;
            int row = rowBase + r;
            float4 v = make_float4(0.f, 0.f, 0.f, 0.f);
            if (row < nrows) {
                v = *(const float4*)(A + (size_t)row * K + k0 + kq * 4);
                if (FIRST) {
                    float ro = rs_out[row];
                    v.x *= ro; v.y *= ro; v.z *= ro; v.w *= ro;
                } else {
                    float ri = rs_in[row];
                    float ro = rs_out[row];
                    int kk = k0 + kq * 4;
                    v.x = lrelu(fmaf(v.x, ri, bprev[kk + 0])) * ro;
                    v.y = lrelu(fmaf(v.y, ri, bprev[kk + 1])) * ro;
                    v.z = lrelu(fmaf(v.z, ri, bprev[kk + 2])) * ro;
                    v.w = lrelu(fmaf(v.w, ri, bprev[kk + 3])) * ro;
                }
            }
            uint4 w0, w1;
            w0.x = f2tf32(v.x); w0.y = f2tf32(v.x - __uint_as_float(w0.x));
            w0.z = f2tf32(v.y); w0.w = f2tf32(v.y - __uint_as_float(w0.z));
            w1.x = f2tf32(v.z); w1.y = f2tf32(v.z - __uint_as_float(w1.x));
            w1.z = f2tf32(v.w); w1.w = f2tf32(v.w - __uint_as_float(w1.z));
            *(uint4*)(As + r * S2 + kq * 4)     = w0;
            *(uint4*)(As + r * S2 + kq * 4 + 2) = w1;
        }
        // ---- B tile ----
        constexpr int BSLOTS = BN * 16;
        constexpr int BPER = BSLOTS / 256;
#pragma unroll
        for (int i = 0; i < BPER; i++) {
            int lin = tid + i * 256;
            int n = lin >> 4;
            int q = lin & 15;
            uint4 v = *(const uint4*)(Bt + (size_t)n * K + k0 + q * 2);
            *(uint4*)(Bs + n * S2 + q * 2) = v;
        }
        __syncthreads();

        // ---- compute: 4 k-steps of 8 ----
#pragma unroll
        for (int ks = 0; ks < 4; ks++) {
            const int kk = ks * 8;
            uint32_t ah[MF][4], al[MF][4];
#pragma unroll
            for (int mf = 0; mf < MF; mf++) {
                int r = wm * WM + mf * 16 + g;
                int c = kk + t4;
                uint2 v0 = As[r * S2 + c];
                uint2 v1 = As[(r + 8) * S2 + c];
                uint2 v2 = As[r * S2 + c + 4];
                uint2 v3 = As[(r + 8) * S2 + c + 4];
                ah[mf][0] = v0.x; al[mf][0] = v0.y;
                ah[mf][1] = v1.x; al[mf][1] = v1.y;
                ah[mf][2] = v2.x; al[mf][2] = v2.y;
                ah[mf][3] = v3.x; al[mf][3] = v3.y;
            }
            uint32_t bh[NF][2], bl[NF][2];
#pragma unroll
            for (int nf = 0; nf < NF; nf++) {
                int n = wn * WN + nf * 8 + g;
                uint2 u0 = Bs[n * S2 + kk + t4];
                uint2 u1 = Bs[n * S2 + kk + t4 + 4];
                bh[nf][0] = u0.x; bl[nf][0] = u0.y;
                bh[nf][1] = u1.x; bl[nf][1] = u1.y;
            }
#pragma unroll
            for (int mf = 0; mf < MF; mf++)
#pragma unroll
                for (int nf = 0; nf < NF; nf++) {
                    mma_tf32(acc[mf][nf], ah[mf], bh[nf]);
                    mma_tf32(acc[mf][nf], al[mf], bh[nf]);
                    mma_tf32(acc[mf][nf], ah[mf], bl[nf]);
                }
        }
        __syncthreads();
    }

    // ---- store ----
#pragma unroll
    for (int mf = 0; mf < MF; mf++) {
#pragma unroll
        for (int nf = 0; nf < NF; nf++) {
            int r0 = rowBase + wm * WM + mf * 16 + g;
            int col = wn * WN + nf * 8 + t4 * 2;
            if (r0 < nrows)
                *(float2*)(out + (size_t)r0 * BN + col) =
                    make_float2(acc[mf][nf][0], acc[mf][nf][1]);
            if (r0 + 8 < nrows)
                *(float2*)(out + (size_t)(r0 + 8) * BN + col) =
                    make_float2(acc[mf][nf][2], acc[mf][nf][3]);
        }
    }
}

// ---------------------------------------------------------------------------
// CSR gather aggregation (unrolled x4)
// ---------------------------------------------------------------------------
__global__ __launch_bounds__(256)
void gather128(const int* __restrict__ row_start, const int* __restrict__ csr,
               const float* __restrict__ h, float* __restrict__ agg, int N)
{
    int warp = (blockIdx.x * blockDim.x + threadIdx.x) >> 5;
    int lane = threadIdx.x & 31;
    if (warp >= N) return;
    int start = row_start[warp];
    int end   = row_start[warp + 1];
    float4 acc = make_float4(0.f, 0.f, 0.f, 0.f);
    int j = start;
    for (; j + 3 < end; j += 4) {
        int s0 = __ldg(&csr[j]);
        int s1 = __ldg(&csr[j + 1]);
        int s2 = __ldg(&csr[j + 2]);
        int s3 = __ldg(&csr[j + 3]);
        float4 v0 = *(const float4*)(h + (size_t)s0 * 128 + lane * 4);
        float4 v1 = *(const float4*)(h + (size_t)s1 * 128 + lane * 4);
        float4 v2 = *(const float4*)(h + (size_t)s2 * 128 + lane * 4);
        float4 v3 = *(const float4*)(h + (size_t)s3 * 128 + lane * 4);
        acc.x += (v0.x + v1.x) + (v2.x + v3.x);
        acc.y += (v0.y + v1.y) + (v2.y + v3.y);
        acc.z += (v0.z + v1.z) + (v2.z + v3.z);
        acc.w += (v0.w + v1.w) + (v2.w + v3.w);
    }
    for (; j < end; j++) {
        int s0 = __ldg(&csr[j]);
        float4 v0 = *(const float4*)(h + (size_t)s0 * 128 + lane * 4);
        acc.x += v0.x; acc.y += v0.y; acc.z += v0.z; acc.w += v0.w;
    }
    *(float4*)(agg + (size_t)warp * 128 + lane * 4) = acc;
}

__global__ __launch_bounds__(256)
void gather64(const int* __restrict__ row_start, const int* __restrict__ csr,
              const float* __restrict__ h, float* __restrict__ agg, int N)
{
    int warp = (blockIdx.x * blockDim.x + threadIdx.x) >> 5;
    int lane = threadIdx.x & 31;
    if (warp >= N) return;
    int start = row_start[warp];
    int end   = row_start[warp + 1];
    float2 acc = make_float2(0.f, 0.f);
    int j = start;
    for (; j + 3 < end; j += 4) {
        int s0 = __ldg(&csr[j]);
        int s1 = __ldg(&csr[j + 1]);
        int s2 = __ldg(&csr[j + 2]);
        int s3 = __ldg(&csr[j + 3]);
        float2 v0 = *(const float2*)(h + (size_t)s0 * 64 + lane * 2);
        float2 v1 = *(const float2*)(h + (size_t)s1 * 64 + lane * 2);
        float2 v2 = *(const float2*)(h + (size_t)s2 * 64 + lane * 2);
        float2 v3 = *(const float2*)(h + (size_t)s3 * 64 + lane * 2);
        acc.x += (v0.x + v1.x) + (v2.x + v3.x);
        acc.y += (v0.y + v1.y) + (v2.y + v3.y);
    }
    for (; j < end; j++) {
        int s0 = __ldg(&csr[j]);
        float2 v0 = *(const float2*)(h + (size_t)s0 * 64 + lane * 2);
        acc.x += v0.x; acc.y += v0.y;
    }
    *(float2*)(agg + (size_t)warp * 64 + lane * 2) = acc;
}

// Final-layer gather with fused epilogue: out = lrelu(acc * rs_in + b2)
__global__ __launch_bounds__(256)
void gather64_epi(const int* __restrict__ row_start, const int* __restrict__ csr,
                  const float* __restrict__ h, const float* __restrict__ rs_in,
                  const float* __restrict__ b, float* __restrict__ out, int N)
{
    int warp = (blockIdx.x * blockDim.x + threadIdx.x) >> 5;
    int lane = threadIdx.x & 31;
    if (warp >= N) return;
    int start = row_start[warp];
    int end   = row_start[warp + 1];
    float2 acc = make_float2(0.f, 0.f);
    int j = start;
    for (; j + 3 < end; j += 4) {
        int s0 = __ldg(&csr[j]);
        int s1 = __ldg(&csr[j + 1]);
        int s2 = __ldg(&csr[j + 2]);
        int s3 = __ldg(&csr[j + 3]);
        float2 v0 = *(const float2*)(h + (size_t)s0 * 64 + lane * 2);
        float2 v1 = *(const float2*)(h + (size_t)s1 * 64 + lane * 2);
        float2 v2 = *(const float2*)(h + (size_t)s2 * 64 + lane * 2);
        float2 v3 = *(const float2*)(h + (size_t)s3 * 64 + lane * 2);
        acc.x += (v0.x + v1.x) + (v2.x + v3.x);
        acc.y += (v0.y + v1.y) + (v2.y + v3.y);
    }
    for (; j < end; j++) {
        int s0 = __ldg(&csr[j]);
        float2 v0 = *(const float2*)(h + (size_t)s0 * 64 + lane * 2);
        acc.x += v0.x; acc.y += v0.y;
    }
    float ri = rs_in[warp];
    int c = lane * 2;
    float2 o;
    o.x = lrelu(fmaf(acc.x, ri, b[c + 0]));
    o.y = lrelu(fmaf(acc.y, ri, b[c + 1]));
    *(float2*)(out + (size_t)warp * 64 + c) = o;
}

// ---------------------------------------------------------------------------
// Launch
// ---------------------------------------------------------------------------
static inline int cdiv(int a, int b) { return (a + b - 1) / b; }

extern "C" void kernel_launch(void* const* d_in, const int* in_sizes, int n_in,
                              void* d_out, int out_size)
{
    const float* n_feat = (const float*)d_in[0];
    const int*   src    = (const int*)  d_in[1];
    const int*   dst    = (const int*)  d_in[2];
    const float* W0     = (const float*)d_in[3];
    const float* b0     = (const float*)d_in[4];
    const float* W1     = (const float*)d_in[5];
    const float* b1     = (const float*)d_in[6];
    const float* W2     = (const float*)d_in[7];
    const float* b2     = (const float*)d_in[8];
    float* out = (float*)d_out;

    const int N = in_sizes[0] / 128;
    const int E = in_sizes[1];

    float *d_h, *d_agg, *d_rso, *d_rsi;
    int *d_indeg, *d_excl, *d_rs, *d_cur, *d_csr, *d_bsum;
    uint2 *d_bt;
    cudaGetSymbolAddress((void**)&d_h,    g_h);
    cudaGetSymbolAddress((void**)&d_agg,  g_agg);
    cudaGetSymbolAddress((void**)&d_rso,  g_rs_out);
    cudaGetSymbolAddress((void**)&d_rsi,  g_rs_in);
    cudaGetSymbolAddress((void**)&d_indeg, g_indeg);
    cudaGetSymbolAddress((void**)&d_excl, g_excl);
    cudaGetSymbolAddress((void**)&d_rs,   g_row_start);
    cudaGetSymbolAddress((void**)&d_cur,  g_cursor);
    cudaGetSymbolAddress((void**)&d_csr,  g_csr_src);
    cudaGetSymbolAddress((void**)&d_bsum, g_bsum);
    cudaGetSymbolAddress((void**)&d_bt,   g_bt);

    constexpr int SMEM_128 = (128 + 128) * 36 * 8;  // 73728
    constexpr int SMEM_64  = (128 + 64) * 36 * 8;   // 55296

    static cudaStream_t s2 = nullptr;
    static cudaEvent_t ev0 = nullptr, ev1 = nullptr;
    if (!s2) {
        cudaFuncSetAttribute(gemm_mma<128, 128, true>,
                             cudaFuncAttributeMaxDynamicSharedMemorySize, SMEM_128);
        cudaFuncSetAttribute(gemm_mma<128, 64, false>,
                             cudaFuncAttributeMaxDynamicSharedMemorySize, SMEM_64);
        cudaFuncSetAttribute(gemm_mma<64, 64, false>,
                             cudaFuncAttributeMaxDynamicSharedMemorySize, SMEM_64);
        cudaStreamCreateWithFlags(&s2, cudaStreamNonBlocking);
        cudaEventCreateWithFlags(&ev0, cudaEventDisableTiming);
        cudaEventCreateWithFlags(&ev1, cudaEventDisableTiming);
    }

    const int gemm_blocks = cdiv(N, 128);
    const int gw_blocks = cdiv(N, 8);
    const int nb = cdiv(N, 1024);

    // ---- main stream head (launches 1-6; #6 = gemm0 for ncu -s 5) ----
    cudaMemsetAsync(d_indeg, 0, (size_t)N * sizeof(int));                      // 1
    cudaMemsetAsync(d_rso, 0, (size_t)N * sizeof(float));                      // 2
    deg_kernel<<<cdiv(E, 256), 256>>>(src, dst, d_rso, d_indeg, E);            // 3
    cudaEventRecord(ev0, 0);  // fork point: indeg ready
    rsqrt_kernel<<<cdiv(N, 256), 256>>>(d_rso, d_indeg, d_rsi, N);             // 4
    split_w<<<cdiv(128 * 128, 256), 256>>>(W0, d_bt, 128, 128);                // 5
    gemm_mma<128, 128, true><<<gemm_blocks, 256, SMEM_128>>>(                  // 6
        n_feat, d_bt, nullptr, d_rso, d_rsi, d_h, N);

    // ---- s2: CSR chain, concurrent with rsqrt/split_w/gemm0 ----
    cudaStreamWaitEvent(s2, ev0, 0);
    scan_block<<<nb, 256, 0, s2>>>(d_indeg, d_excl, d_bsum, N);
    scan_bsum<<<1, 512, 0, s2>>>(d_bsum, nb);
    scan_add<<<cdiv(N, 256), 256, 0, s2>>>(d_excl, d_bsum, d_rs, d_cur, N, E);
    fill_csr<<<cdiv(E, 256), 256, 0, s2>>>(src, dst, d_cur, d_csr, E);
    cudaEventRecord(ev1, s2);

    // ---- join: gathers need the CSR ----
    cudaStreamWaitEvent(0, ev1, 0);
    gather128<<<gw_blocks, 256>>>(d_rs, d_csr, d_h, d_agg, N);

    // --- layer 1: 128 -> 64 ---
    split_w<<<cdiv(128 * 64, 256), 256>>>(W1, d_bt, 128, 64);
    gemm_mma<128, 64, false><<<gemm_blocks, 256, SMEM_64>>>(
        d_agg, d_bt, b0, d_rso, d_rsi, d_h, N);
    gather64<<<gw_blocks, 256>>>(d_rs, d_csr, d_h, d_agg, N);

    // --- layer 2: 64 -> 64 ---
    split_w<<<cdiv(64 * 64, 256), 256>>>(W2, d_bt, 64, 64);
    gemm_mma<64, 64, false><<<gemm_blocks, 256, SMEM_64>>>(
        d_agg, d_bt, b1, d_rso, d_rsi, d_h, N);
    gather64_epi<<<gw_blocks, 256>>>(d_rs, d_csr, d_h, d_rsi, b2, out, N);
}

// round 7
// speedup vs baseline: 1.2070x; 1.1905x over previous
#include <cuda_runtime.h>
#include <cuda_bf16.h>
#include <cuda_fp16.h>
#include <cstdint>

#define LEAKY 0.01f

static constexpr int MAX_N = 100000;
static constexpr int MAX_E = 1600000;

// Scratch (module-scope device globals; allocation inside kernel_launch is forbidden)
__device__ float g_h[(size_t)MAX_N * 128];    // GEMM output / gather source
__device__ float g_agg[(size_t)MAX_N * 128];  // gather destination / next GEMM input
__device__ float g_rs_out[MAX_N];             // rsqrt(max(out_deg,1))
__device__ float g_rs_in[MAX_N];              // rsqrt(max(in_deg,1))
__device__ int   g_indeg[MAX_N];              // int in-degree counts
__device__ int   g_excl[MAX_N];               // scan scratch
__device__ int   g_row_start[MAX_N + 1];      // CSR row offsets (by dst)
__device__ int   g_cursor[MAX_N];             // CSR fill cursors
__device__ int   g_csr_src[MAX_E];            // CSR column (src node) array
__device__ int   g_bsum[512];                 // scan block sums
__device__ uint2 g_bt[128 * 64];              // W^T fp16 (hi2,lo2) packed [n][k/2]

__device__ __forceinline__ float lrelu(float t) {
    return (t >= 0.f) ? t : LEAKY * t;
}

__device__ __forceinline__ uint32_t h2bits(__half2 h) {
    return *reinterpret_cast<uint32_t*>(&h);
}

// split two floats into fp16 hi/lo planes packed as half2 words
__device__ __forceinline__ uint2 split2(float a, float b) {
    __half2 h = __floats2half2_rn(a, b);
    float la = a - __low2float(h);
    float lb = b - __high2float(h);
    __half2 l = __floats2half2_rn(la, lb);
    return make_uint2(h2bits(h), h2bits(l));
}

__device__ __forceinline__ void mma_f16(float* d, const uint32_t* a, const uint32_t* b) {
    asm volatile(
        "mma.sync.aligned.m16n8k16.row.col.f32.f16.f16.f32 "
        "{%0,%1,%2,%3}, {%4,%5,%6,%7}, {%8,%9}, {%0,%1,%2,%3};"
        : "+f"(d[0]), "+f"(d[1]), "+f"(d[2]), "+f"(d[3])
        : "r"(a[0]), "r"(a[1]), "r"(a[2]), "r"(a[3]), "r"(b[0]), "r"(b[1]));
}

// ---------------------------------------------------------------------------
// Degrees: single E pass, both atomics
// ---------------------------------------------------------------------------
__global__ void deg_kernel(const int* __restrict__ src, const int* __restrict__ dst,
                           float* __restrict__ dout, int* __restrict__ indeg, int E) {
    int i = blockIdx.x * blockDim.x + threadIdx.x;
    if (i < E) {
        atomicAdd(&dout[src[i]], 1.0f);
        atomicAdd(&indeg[dst[i]], 1);
    }
}

__global__ void rsqrt_kernel(float* __restrict__ dout, const int* __restrict__ indeg,
                             float* __restrict__ rsin, int N) {
    int i = blockIdx.x * blockDim.x + threadIdx.x;
    if (i < N) {
        dout[i] = rsqrtf(fmaxf(dout[i], 1.0f));
        rsin[i] = rsqrtf(fmaxf((float)indeg[i], 1.0f));
    }
}

// ---------------------------------------------------------------------------
// Exclusive scan over in-degrees
// ---------------------------------------------------------------------------
__global__ void scan_block(const int* __restrict__ deg, int* __restrict__ excl,
                           int* __restrict__ bsum, int N) {
    __shared__ int ts[256];
    int tid = threadIdx.x;
    int base = blockIdx.x * 1024 + tid * 4;
    int v[4];
    int sum = 0;
#pragma unroll
    for (int i = 0; i < 4; i++) {
        int idx = base + i;
        v[i] = (idx < N) ? deg[idx] : 0;
        sum += v[i];
    }
    ts[tid] = sum;
    __syncthreads();
    for (int off = 1; off < 256; off <<= 1) {
        int t = (tid >= off) ? ts[tid - off] : 0;
        __syncthreads();
        ts[tid] += t;
        __syncthreads();
    }
    if (tid == 255) bsum[blockIdx.x] = ts[255];
    int run = ts[tid] - sum;
#pragma unroll
    for (int i = 0; i < 4; i++) {
        int idx = base + i;
        if (idx < N) excl[idx] = run;
        run += v[i];
    }
}

__global__ void scan_bsum(int* __restrict__ bsum, int nb) {
    __shared__ int s[512];
    int tid = threadIdx.x;
    int v = (tid < nb) ? bsum[tid] : 0;
    s[tid] = v;
    __syncthreads();
    for (int off = 1; off < 512; off <<= 1) {
        int t = (tid >= off) ? s[tid - off] : 0;
        __syncthreads();
        s[tid] += t;
        __syncthreads();
    }
    if (tid < nb) bsum[tid] = s[tid] - v;
}

__global__ void scan_add(const int* __restrict__ excl, const int* __restrict__ bsum,
                         int* __restrict__ row_start, int* __restrict__ cursor,
                         int N, int E) {
    int i = blockIdx.x * blockDim.x + threadIdx.x;
    if (i < N) {
        int v = excl[i] + bsum[i >> 10];
        row_start[i] = v;
        cursor[i] = v;
    }
    if (i == 0) row_start[N] = E;
}

__global__ void fill_csr(const int* __restrict__ src, const int* __restrict__ dst,
                         int* __restrict__ cursor, int* __restrict__ csr_src, int E) {
    int e = blockIdx.x * blockDim.x + threadIdx.x;
    if (e < E) {
        int pos = atomicAdd(&cursor[dst[e]], 1);
        csr_src[pos] = src[e];
    }
}

// ---------------------------------------------------------------------------
// W split: bt[n*(K/2)+j] = fp16 hi/lo half2 of (W[2j][n], W[2j+1][n])
// ---------------------------------------------------------------------------
__global__ void split_w(const float* __restrict__ W, uint2* __restrict__ bt, int K, int BN) {
    int idx = blockIdx.x * blockDim.x + threadIdx.x;
    int KP = K >> 1;
    if (idx >= BN * KP) return;
    int n = idx / KP;
    int j = idx % KP;
    float w0 = W[(size_t)(2 * j) * BN + n];
    float w1 = W[(size_t)(2 * j + 1) * BN + n];
    bt[idx] = split2(w0, w1);
}

// ---------------------------------------------------------------------------
// fp16 3-term split GEMM (m16n8k16): out[N,BN] = pre(A)[N,K] @ W[K,BN]
//   FIRST=true :  pre(a) = a * rs_out[row]
//   FIRST=false:  pre(a) = lrelu(a * rs_in[row] + bprev[k]) * rs_out[row]
// B (W^T, hi/lo fp16 planes) fully SMEM-resident; A in BK=32 chunks with
// hoisted LDG. SMEM elements uint2{hi2,lo2}; strides ≡ 4 mod 16 uint2
// (conflict-free LDS.64 fragment loads). 256 threads, BM=128.
// ---------------------------------------------------------------------------
template<int K, int BN, bool FIRST>
__global__ __launch_bounds__(256, 2)
void gemm_mma(const float* __restrict__ A, const uint2* __restrict__ Bt,
              const float* __restrict__ bprev,
              const float* __restrict__ rs_out, const float* __restrict__ rs_in,
              float* __restrict__ out, int nrows)
{
    constexpr int WARPS_M = (BN == 128) ? 2 : 4;
    constexpr int WM = 128 / WARPS_M;   // 64 or 32
    constexpr int WN = 32;
    constexpr int MF = WM / 16;         // 4 or 2
    constexpr int NF = 4;
    constexpr int KP = K / 2;           // fp16 pairs per row
    constexpr int AS2 = 20;             // A row stride in uint2 (16 pairs + 4 pad)
    constexpr int BS2 = KP + 4;         // B row stride in uint2 (68 or 36)
    constexpr int NCHUNK = K / 32;

    extern __shared__ __align__(16) uint2 smem2[];
    uint2* As = smem2;               // [128][AS2]
    uint2* Bs = smem2 + 128 * AS2;   // [BN][BS2]

    const int tid = threadIdx.x;
    const int wid = tid >> 5;
    const int lane = tid & 31;
    const int wm = wid % WARPS_M;
    const int wn = wid / WARPS_M;
    const int rowBase = blockIdx.x * 128;
    const int g = lane >> 2;
    const int t4 = lane & 3;

    // ---- load resident B (whole K x BN, hi/lo packed) ----
    constexpr int BU4 = BN * KP / 2;  // uint4 count
#pragma unroll 4
    for (int idx = tid; idx < BU4; idx += 256) {
        int lin = idx * 2;
        int n = lin / KP;
        int j = lin % KP;
        uint4 v = *(const uint4*)(Bt + (size_t)n * KP + j);
        *(uint4*)(Bs + n * BS2 + j) = v;
    }

    // ---- A chunk staging ----
    float4 q[4];
    int a_r[4], a_kq[4];
#pragma unroll
    for (int i = 0; i < 4; i++) {
        int lin = tid + i * 256;
        a_r[i] = lin >> 3;
        a_kq[i] = lin & 7;
    }

    auto load_a = [&](int c) {
#pragma unroll
        for (int i = 0; i < 4; i++) {
            int row = rowBase + a_r[i];
            float4 v = make_float4(0.f, 0.f, 0.f, 0.f);
            if (row < nrows) {
                v = *(const float4*)(A + (size_t)row * K + c * 32 + a_kq[i] * 4);
                if (FIRST) {
                    float ro = rs_out[row];
                    v.x *= ro; v.y *= ro; v.z *= ro; v.w *= ro;
                } else {
                    float ri = rs_in[row];
                    float ro = rs_out[row];
                    int kk = c * 32 + a_kq[i] * 4;
                    v.x = lrelu(fmaf(v.x, ri, bprev[kk + 0])) * ro;
                    v.y = lrelu(fmaf(v.y, ri, bprev[kk + 1])) * ro;
                    v.z = lrelu(fmaf(v.z, ri, bprev[kk + 2])) * ro;
                    v.w = lrelu(fmaf(v.w, ri, bprev[kk + 3])) * ro;
                }
            }
            q[i] = v;
        }
    };
    auto sts_a = [&]() {
#pragma unroll
        for (int i = 0; i < 4; i++) {
            uint2 e0 = split2(q[i].x, q[i].y);
            uint2 e1 = split2(q[i].z, q[i].w);
            uint4 st = make_uint4(e0.x, e0.y, e1.x, e1.y);
            *(uint4*)(As + a_r[i] * AS2 + a_kq[i] * 2) = st;
        }
    };

    load_a(0);
    sts_a();
    __syncthreads();

    float acc[MF][NF][4];
#pragma unroll
    for (int i = 0; i < MF; i++)
#pragma unroll
        for (int j = 0; j < NF; j++)
#pragma unroll
            for (int c = 0; c < 4; c++) acc[i][j][c] = 0.f;

#pragma unroll
    for (int c = 0; c < NCHUNK; c++) {
        if (c + 1 < NCHUNK) load_a(c + 1);  // hoisted: LDG overlaps compute

#pragma unroll
        for (int ks = 0; ks < 2; ks++) {
            uint32_t ah[MF][4], al[MF][4];
#pragma unroll
            for (int mf = 0; mf < MF; mf++) {
                int r = wm * WM + mf * 16 + g;
                int e = ks * 8 + t4;
                uint2 v0 = As[r * AS2 + e];
                uint2 v1 = As[(r + 8) * AS2 + e];
                uint2 v2 = As[r * AS2 + e + 4];
                uint2 v3 = As[(r + 8) * AS2 + e + 4];
                ah[mf][0] = v0.x; al[mf][0] = v0.y;
                ah[mf][1] = v1.x; al[mf][1] = v1.y;
                ah[mf][2] = v2.x; al[mf][2] = v2.y;
                ah[mf][3] = v3.x; al[mf][3] = v3.y;
            }
            uint32_t bh[NF][2], bl[NF][2];
            const int eb = c * 16 + ks * 8 + t4;
#pragma unroll
            for (int nf = 0; nf < NF; nf++) {
                int n = wn * WN + nf * 8 + g;
                uint2 u0 = Bs[n * BS2 + eb];
                uint2 u1 = Bs[n * BS2 + eb + 4];
                bh[nf][0] = u0.x; bl[nf][0] = u0.y;
                bh[nf][1] = u1.x; bl[nf][1] = u1.y;
            }
#pragma unroll
            for (int mf = 0; mf < MF; mf++)
#pragma unroll
                for (int nf = 0; nf < NF; nf++) {
                    mma_f16(acc[mf][nf], ah[mf], bh[nf]);
                    mma_f16(acc[mf][nf], al[mf], bh[nf]);
                    mma_f16(acc[mf][nf], ah[mf], bl[nf]);
                }
        }
        __syncthreads();
        if (c + 1 < NCHUNK) {
            sts_a();
            __syncthreads();
        }
    }

    // ---- store ----
#pragma unroll
    for (int mf = 0; mf < MF; mf++) {
#pragma unroll
        for (int nf = 0; nf < NF; nf++) {
            int r0 = rowBase + wm * WM + mf * 16 + g;
            int col = wn * WN + nf * 8 + t4 * 2;
            if (r0 < nrows)
                *(float2*)(out + (size_t)r0 * BN + col) =
                    make_float2(acc[mf][nf][0], acc[mf][nf][1]);
            if (r0 + 8 < nrows)
                *(float2*)(out + (size_t)(r0 + 8) * BN + col) =
                    make_float2(acc[mf][nf][2], acc[mf][nf][3]);
        }
    }
}

// ---------------------------------------------------------------------------
// CSR gather aggregation (unrolled x4)
// ---------------------------------------------------------------------------
__global__ __launch_bounds__(256)
void gather128(const int* __restrict__ row_start, const int* __restrict__ csr,
               const float* __restrict__ h, float* __restrict__ agg, int N)
{
    int warp = (blockIdx.x * blockDim.x + threadIdx.x) >> 5;
    int lane = threadIdx.x & 31;
    if (warp >= N) return;
    int start = row_start[warp];
    int end   = row_start[warp + 1];
    float4 acc = make_float4(0.f, 0.f, 0.f, 0.f);
    int j = start;
    for (; j + 3 < end; j += 4) {
        int s0 = __ldg(&csr[j]);
        int s1 = __ldg(&csr[j + 1]);
        int s2 = __ldg(&csr[j + 2]);
        int s3 = __ldg(&csr[j + 3]);
        float4 v0 = *(const float4*)(h + (size_t)s0 * 128 + lane * 4);
        float4 v1 = *(const float4*)(h + (size_t)s1 * 128 + lane * 4);
        float4 v2 = *(const float4*)(h + (size_t)s2 * 128 + lane * 4);
        float4 v3 = *(const float4*)(h + (size_t)s3 * 128 + lane * 4);
        acc.x += (v0.x + v1.x) + (v2.x + v3.x);
        acc.y += (v0.y + v1.y) + (v2.y + v3.y);
        acc.z += (v0.z + v1.z) + (v2.z + v3.z);
        acc.w += (v0.w + v1.w) + (v2.w + v3.w);
    }
    for (; j < end; j++) {
        int s0 = __ldg(&csr[j]);
        float4 v0 = *(const float4*)(h + (size_t)s0 * 128 + lane * 4);
        acc.x += v0.x; acc.y += v0.y; acc.z += v0.z; acc.w += v0.w;
    }
    *(float4*)(agg + (size_t)warp * 128 + lane * 4) = acc;
}

__global__ __launch_bounds__(256)
void gather64(const int* __restrict__ row_start, const int* __restrict__ csr,
              const float* __restrict__ h, float* __restrict__ agg, int N)
{
    int warp = (blockIdx.x * blockDim.x + threadIdx.x) >> 5;
    int lane = threadIdx.x & 31;
    if (warp >= N) return;
    int start = row_start[warp];
    int end   = row_start[warp + 1];
    float2 acc = make_float2(0.f, 0.f);
    int j = start;
    for (; j + 3 < end; j += 4) {
        int s0 = __ldg(&csr[j]);
        int s1 = __ldg(&csr[j + 1]);
        int s2 = __ldg(&csr[j + 2]);
        int s3 = __ldg(&csr[j + 3]);
        float2 v0 = *(const float2*)(h + (size_t)s0 * 64 + lane * 2);
        float2 v1 = *(const float2*)(h + (size_t)s1 * 64 + lane * 2);
        float2 v2 = *(const float2*)(h + (size_t)s2 * 64 + lane * 2);
        float2 v3 = *(const float2*)(h + (size_t)s3 * 64 + lane * 2);
        acc.x += (v0.x + v1.x) + (v2.x + v3.x);
        acc.y += (v0.y + v1.y) + (v2.y + v3.y);
    }
    for (; j < end; j++) {
        int s0 = __ldg(&csr[j]);
        float2 v0 = *(const float2*)(h + (size_t)s0 * 64 + lane * 2);
        acc.x += v0.x; acc.y += v0.y;
    }
    *(float2*)(agg + (size_t)warp * 64 + lane * 2) = acc;
}

// Final-layer gather with fused epilogue: out = lrelu(acc * rs_in + b2)
__global__ __launch_bounds__(256)
void gather64_epi(const int* __restrict__ row_start, const int* __restrict__ csr,
                  const float* __restrict__ h, const float* __restrict__ rs_in,
                  const float* __restrict__ b, float* __restrict__ out, int N)
{
    int warp = (blockIdx.x * blockDim.x + threadIdx.x) >> 5;
    int lane = threadIdx.x & 31;
    if (warp >= N) return;
    int start = row_start[warp];
    int end   = row_start[warp + 1];
    float2 acc = make_float2(0.f, 0.f);
    int j = start;
    for (; j + 3 < end; j += 4) {
        int s0 = __ldg(&csr[j]);
        int s1 = __ldg(&csr[j + 1]);
        int s2 = __ldg(&csr[j + 2]);
        int s3 = __ldg(&csr[j + 3]);
        float2 v0 = *(const float2*)(h + (size_t)s0 * 64 + lane * 2);
        float2 v1 = *(const float2*)(h + (size_t)s1 * 64 + lane * 2);
        float2 v2 = *(const float2*)(h + (size_t)s2 * 64 + lane * 2);
        float2 v3 = *(const float2*)(h + (size_t)s3 * 64 + lane * 2);
        acc.x += (v0.x + v1.x) + (v2.x + v3.x);
        acc.y += (v0.y + v1.y) + (v2.y + v3.y);
    }
    for (; j < end; j++) {
        int s0 = __ldg(&csr[j]);
        float2 v0 = *(const float2*)(h + (size_t)s0 * 64 + lane * 2);
        acc.x += v0.x; acc.y += v0.y;
    }
    float ri = rs_in[warp];
    int c = lane * 2;
    float2 o;
    o.x = lrelu(fmaf(acc.x, ri, b[c + 0]));
    o.y = lrelu(fmaf(acc.y, ri, b[c + 1]));
    *(float2*)(out + (size_t)warp * 64 + c) = o;
}

// ---------------------------------------------------------------------------
// Launch
// ---------------------------------------------------------------------------
static inline int cdiv(int a, int b) { return (a + b - 1) / b; }

extern "C" void kernel_launch(void* const* d_in, const int* in_sizes, int n_in,
                              void* d_out, int out_size)
{
    const float* n_feat = (const float*)d_in[0];
    const int*   src    = (const int*)  d_in[1];
    const int*   dst    = (const int*)  d_in[2];
    const float* W0     = (const float*)d_in[3];
    const float* b0     = (const float*)d_in[4];
    const float* W1     = (const float*)d_in[5];
    const float* b1     = (const float*)d_in[6];
    const float* W2     = (const float*)d_in[7];
    const float* b2     = (const float*)d_in[8];
    float* out = (float*)d_out;

    const int N = in_sizes[0] / 128;
    const int E = in_sizes[1];

    float *d_h, *d_agg, *d_rso, *d_rsi;
    int *d_indeg, *d_excl, *d_rs, *d_cur, *d_csr, *d_bsum;
    uint2 *d_bt;
    cudaGetSymbolAddress((void**)&d_h,    g_h);
    cudaGetSymbolAddress((void**)&d_agg,  g_agg);
    cudaGetSymbolAddress((void**)&d_rso,  g_rs_out);
    cudaGetSymbolAddress((void**)&d_rsi,  g_rs_in);
    cudaGetSymbolAddress((void**)&d_indeg, g_indeg);
    cudaGetSymbolAddress((void**)&d_excl, g_excl);
    cudaGetSymbolAddress((void**)&d_rs,   g_row_start);
    cudaGetSymbolAddress((void**)&d_cur,  g_cursor);
    cudaGetSymbolAddress((void**)&d_csr,  g_csr_src);
    cudaGetSymbolAddress((void**)&d_bsum, g_bsum);
    cudaGetSymbolAddress((void**)&d_bt,   g_bt);

    // SMEM: (128*AS2 + BN*BS2) * 8 bytes
    constexpr int SMEM_L0 = (128 * 20 + 128 * 68) * 8;  // 90112
    constexpr int SMEM_L1 = (128 * 20 + 64 * 68) * 8;   // 55296
    constexpr int SMEM_L2 = (128 * 20 + 64 * 36) * 8;   // 38912

    static cudaStream_t s2 = nullptr;
    static cudaEvent_t ev0 = nullptr, ev1 = nullptr;
    if (!s2) {
        cudaFuncSetAttribute(gemm_mma<128, 128, true>,
                             cudaFuncAttributeMaxDynamicSharedMemorySize, SMEM_L0);
        cudaFuncSetAttribute(gemm_mma<128, 64, false>,
                             cudaFuncAttributeMaxDynamicSharedMemorySize, SMEM_L1);
        cudaFuncSetAttribute(gemm_mma<64, 64, false>,
                             cudaFuncAttributeMaxDynamicSharedMemorySize, SMEM_L2);
        cudaStreamCreateWithFlags(&s2, cudaStreamNonBlocking);
        cudaEventCreateWithFlags(&ev0, cudaEventDisableTiming);
        cudaEventCreateWithFlags(&ev1, cudaEventDisableTiming);
    }

    const int gemm_blocks = cdiv(N, 128);
    const int gw_blocks = cdiv(N, 8);
    const int nb = cdiv(N, 1024);

    // ---- main stream head (launches 1-6; #6 = gemm0 for ncu -s 5) ----
    cudaMemsetAsync(d_indeg, 0, (size_t)N * sizeof(int));                      // 1
    cudaMemsetAsync(d_rso, 0, (size_t)N * sizeof(float));                      // 2
    deg_kernel<<<cdiv(E, 256), 256>>>(src, dst, d_rso, d_indeg, E);            // 3
    cudaEventRecord(ev0, 0);  // fork point: indeg ready
    rsqrt_kernel<<<cdiv(N, 256), 256>>>(d_rso, d_indeg, d_rsi, N);             // 4
    split_w<<<cdiv(128 * 64, 256), 256>>>(W0, d_bt, 128, 128);                 // 5
    gemm_mma<128, 128, true><<<gemm_blocks, 256, SMEM_L0>>>(                   // 6
        n_feat, d_bt, nullptr, d_rso, d_rsi, d_h, N);

    // ---- s2: CSR chain, concurrent with rsqrt/split_w/gemm0 ----
    cudaStreamWaitEvent(s2, ev0, 0);
    scan_block<<<nb, 256, 0, s2>>>(d_indeg, d_excl, d_bsum, N);
    scan_bsum<<<1, 512, 0, s2>>>(d_bsum, nb);
    scan_add<<<cdiv(N, 256), 256, 0, s2>>>(d_excl, d_bsum, d_rs, d_cur, N, E);
    fill_csr<<<cdiv(E, 256), 256, 0, s2>>>(src, dst, d_cur, d_csr, E);
    cudaEventRecord(ev1, s2);

    // ---- join: gathers need the CSR ----
    cudaStreamWaitEvent(0, ev1, 0);
    gather128<<<gw_blocks, 256>>>(d_rs, d_csr, d_h, d_agg, N);

    // --- layer 1: 128 -> 64 ---
    split_w<<<cdiv(64 * 64, 256), 256>>>(W1, d_bt, 128, 64);
    gemm_mma<128, 64, false><<<gemm_blocks, 256, SMEM_L1>>>(
        d_agg, d_bt, b0, d_rso, d_rsi, d_h, N);
    gather64<<<gw_blocks, 256>>>(d_rs, d_csr, d_h, d_agg, N);

    // --- layer 2: 64 -> 64 ---
    split_w<<<cdiv(64 * 32, 256), 256>>>(W2, d_bt, 64, 64);
    gemm_mma<64, 64, false><<<gemm_blocks, 256, SMEM_L2>>>(
        d_agg, d_bt, b1, d_rso, d_rsi, d_h, N);
    gather64_epi<<<gw_blocks, 256>>>(d_rs, d_csr, d_h, d_rsi, b2, out, N);
}

// round 8
// speedup vs baseline: 1.2982x; 1.0755x over previous
#include <cuda_runtime.h>
#include <cuda_bf16.h>
#include <cuda_fp16.h>
#include <cstdint>

#define LEAKY 0.01f

static constexpr int MAX_N = 100000;
static constexpr int MAX_E = 1600000;

// Scratch (module-scope device globals; allocation inside kernel_launch is forbidden)
__device__ __half g_h16[(size_t)MAX_N * 128];  // GEMM output (fp16) / gather source
__device__ float  g_agg[(size_t)MAX_N * 128];  // gather destination (fp32) / next GEMM input
__device__ float  g_rs_out[MAX_N];             // rsqrt(max(out_deg,1))
__device__ float  g_rs_in[MAX_N];              // rsqrt(max(in_deg,1))
__device__ int    g_indeg[MAX_N];              // int in-degree counts
__device__ int    g_excl[MAX_N];               // scan scratch
__device__ int    g_row_start[MAX_N + 1];      // CSR row offsets (by dst)
__device__ int    g_cursor[MAX_N];             // CSR fill cursors
__device__ int    g_csr_src[MAX_E];            // CSR column (src node) array
__device__ int    g_bsum[512];                 // scan block sums
__device__ uint2  g_bt[128 * 64];              // W^T fp16 (hi2,lo2) packed [n][k/2]

__device__ __forceinline__ float lrelu(float t) {
    return (t >= 0.f) ? t : LEAKY * t;
}

__device__ __forceinline__ uint32_t h2bits(__half2 h) {
    return *reinterpret_cast<uint32_t*>(&h);
}

// split two floats into fp16 hi/lo planes packed as half2 words
__device__ __forceinline__ uint2 split2(float a, float b) {
    __half2 h = __floats2half2_rn(a, b);
    float la = a - __low2float(h);
    float lb = b - __high2float(h);
    __half2 l = __floats2half2_rn(la, lb);
    return make_uint2(h2bits(h), h2bits(l));
}

__device__ __forceinline__ void mma_f16(float* d, const uint32_t* a, const uint32_t* b) {
    asm volatile(
        "mma.sync.aligned.m16n8k16.row.col.f32.f16.f16.f32 "
        "{%0,%1,%2,%3}, {%4,%5,%6,%7}, {%8,%9}, {%0,%1,%2,%3};"
        : "+f"(d[0]), "+f"(d[1]), "+f"(d[2]), "+f"(d[3])
        : "r"(a[0]), "r"(a[1]), "r"(a[2]), "r"(a[3]), "r"(b[0]), "r"(b[1]));
}

// ---------------------------------------------------------------------------
// Degrees: single E pass, both atomics
// ---------------------------------------------------------------------------
__global__ void deg_kernel(const int* __restrict__ src, const int* __restrict__ dst,
                           float* __restrict__ dout, int* __restrict__ indeg, int E) {
    int i = blockIdx.x * blockDim.x + threadIdx.x;
    if (i < E) {
        atomicAdd(&dout[src[i]], 1.0f);
        atomicAdd(&indeg[dst[i]], 1);
    }
}

__global__ void rsqrt_kernel(float* __restrict__ dout, const int* __restrict__ indeg,
                             float* __restrict__ rsin, int N) {
    int i = blockIdx.x * blockDim.x + threadIdx.x;
    if (i < N) {
        dout[i] = rsqrtf(fmaxf(dout[i], 1.0f));
        rsin[i] = rsqrtf(fmaxf((float)indeg[i], 1.0f));
    }
}

// ---------------------------------------------------------------------------
// Exclusive scan over in-degrees
// ---------------------------------------------------------------------------
__global__ void scan_block(const int* __restrict__ deg, int* __restrict__ excl,
                           int* __restrict__ bsum, int N) {
    __shared__ int ts[256];
    int tid = threadIdx.x;
    int base = blockIdx.x * 1024 + tid * 4;
    int v[4];
    int sum = 0;
#pragma unroll
    for (int i = 0; i < 4; i++) {
        int idx = base + i;
        v[i] = (idx < N) ? deg[idx] : 0;
        sum += v[i];
    }
    ts[tid] = sum;
    __syncthreads();
    for (int off = 1; off < 256; off <<= 1) {
        int t = (tid >= off) ? ts[tid - off] : 0;
        __syncthreads();
        ts[tid] += t;
        __syncthreads();
    }
    if (tid == 255) bsum[blockIdx.x] = ts[255];
    int run = ts[tid] - sum;
#pragma unroll
    for (int i = 0; i < 4; i++) {
        int idx = base + i;
        if (idx < N) excl[idx] = run;
        run += v[i];
    }
}

__global__ void scan_bsum(int* __restrict__ bsum, int nb) {
    __shared__ int s[512];
    int tid = threadIdx.x;
    int v = (tid < nb) ? bsum[tid] : 0;
    s[tid] = v;
    __syncthreads();
    for (int off = 1; off < 512; off <<= 1) {
        int t = (tid >= off) ? s[tid - off] : 0;
        __syncthreads();
        s[tid] += t;
        __syncthreads();
    }
    if (tid < nb) bsum[tid] = s[tid] - v;
}

__global__ void scan_add(const int* __restrict__ excl, const int* __restrict__ bsum,
                         int* __restrict__ row_start, int* __restrict__ cursor,
                         int N, int E) {
    int i = blockIdx.x * blockDim.x + threadIdx.x;
    if (i < N) {
        int v = excl[i] + bsum[i >> 10];
        row_start[i] = v;
        cursor[i] = v;
    }
    if (i == 0) row_start[N] = E;
}

__global__ void fill_csr(const int* __restrict__ src, const int* __restrict__ dst,
                         int* __restrict__ cursor, int* __restrict__ csr_src, int E) {
    int e = blockIdx.x * blockDim.x + threadIdx.x;
    if (e < E) {
        int pos = atomicAdd(&cursor[dst[e]], 1);
        csr_src[pos] = src[e];
    }
}

// ---------------------------------------------------------------------------
// W split: bt[n*(K/2)+j] = fp16 hi/lo half2 of (W[2j][n], W[2j+1][n])
// ---------------------------------------------------------------------------
__global__ void split_w(const float* __restrict__ W, uint2* __restrict__ bt, int K, int BN) {
    int idx = blockIdx.x * blockDim.x + threadIdx.x;
    int KP = K >> 1;
    if (idx >= BN * KP) return;
    int n = idx / KP;
    int j = idx % KP;
    float w0 = W[(size_t)(2 * j) * BN + n];
    float w1 = W[(size_t)(2 * j + 1) * BN + n];
    bt[idx] = split2(w0, w1);
}

// ---------------------------------------------------------------------------
// fp16 3-term split GEMM (m16n8k16): outh[N,BN] = fp16(pre(A)[N,K] @ W[K,BN])
//   FIRST=true :  pre(a) = a * rs_out[row]
//   FIRST=false:  pre(a) = lrelu(a * rs_in[row] + bprev[k]) * rs_out[row]
// B resident in SMEM; A double-buffered (BK=32 chunks), ONE sync per chunk.
// ---------------------------------------------------------------------------
template<int K, int BN, bool FIRST>
__global__ __launch_bounds__(256, 2)
void gemm_mma(const float* __restrict__ A, const uint2* __restrict__ Bt,
              const float* __restrict__ bprev,
              const float* __restrict__ rs_out, const float* __restrict__ rs_in,
              __half* __restrict__ outh, int nrows)
{
    constexpr int WARPS_M = (BN == 128) ? 2 : 4;
    constexpr int WM = 128 / WARPS_M;   // 64 or 32
    constexpr int WN = 32;
    constexpr int MF = WM / 16;         // 4 or 2
    constexpr int NF = 4;
    constexpr int KP = K / 2;           // fp16 pairs per row
    constexpr int AS2 = 20;             // A row stride in uint2 (16 pairs + 4 pad)
    constexpr int BS2 = KP + 4;         // B row stride in uint2
    constexpr int NCHUNK = K / 32;

    extern __shared__ __align__(16) uint2 smem2[];
    uint2* As0 = smem2;                   // [128][AS2] buffer 0
    uint2* As1 = smem2 + 128 * AS2;       // [128][AS2] buffer 1
    uint2* Bs  = smem2 + 2 * 128 * AS2;   // [BN][BS2]

    const int tid = threadIdx.x;
    const int wid = tid >> 5;
    const int lane = tid & 31;
    const int wm = wid % WARPS_M;
    const int wn = wid / WARPS_M;
    const int rowBase = blockIdx.x * 128;
    const int g = lane >> 2;
    const int t4 = lane & 3;

    // ---- load resident B ----
    constexpr int BU4 = BN * KP / 2;
#pragma unroll 4
    for (int idx = tid; idx < BU4; idx += 256) {
        int lin = idx * 2;
        int n = lin / KP;
        int j = lin % KP;
        uint4 v = *(const uint4*)(Bt + (size_t)n * KP + j);
        *(uint4*)(Bs + n * BS2 + j) = v;
    }

    // ---- A chunk staging ----
    float4 q[4];
    int a_r[4], a_kq[4];
#pragma unroll
    for (int i = 0; i < 4; i++) {
        int lin = tid + i * 256;
        a_r[i] = lin >> 3;
        a_kq[i] = lin & 7;
    }

    auto load_a = [&](int c) {
#pragma unroll
        for (int i = 0; i < 4; i++) {
            int row = rowBase + a_r[i];
            float4 v = make_float4(0.f, 0.f, 0.f, 0.f);
            if (row < nrows) {
                v = *(const float4*)(A + (size_t)row * K + c * 32 + a_kq[i] * 4);
                if (FIRST) {
                    float ro = rs_out[row];
                    v.x *= ro; v.y *= ro; v.z *= ro; v.w *= ro;
                } else {
                    float ri = rs_in[row];
                    float ro = rs_out[row];
                    int kk = c * 32 + a_kq[i] * 4;
                    v.x = lrelu(fmaf(v.x, ri, bprev[kk + 0])) * ro;
                    v.y = lrelu(fmaf(v.y, ri, bprev[kk + 1])) * ro;
                    v.z = lrelu(fmaf(v.z, ri, bprev[kk + 2])) * ro;
                    v.w = lrelu(fmaf(v.w, ri, bprev[kk + 3])) * ro;
                }
            }
            q[i] = v;
        }
    };
    auto sts_a = [&](uint2* buf) {
#pragma unroll
        for (int i = 0; i < 4; i++) {
            uint2 e0 = split2(q[i].x, q[i].y);
            uint2 e1 = split2(q[i].z, q[i].w);
            uint4 st = make_uint4(e0.x, e0.y, e1.x, e1.y);
            *(uint4*)(buf + a_r[i] * AS2 + a_kq[i] * 2) = st;
        }
    };

    load_a(0);
    sts_a(As0);
    __syncthreads();

    float acc[MF][NF][4];
#pragma unroll
    for (int i = 0; i < MF; i++)
#pragma unroll
        for (int j = 0; j < NF; j++)
#pragma unroll
            for (int c = 0; c < 4; c++) acc[i][j][c] = 0.f;

#pragma unroll
    for (int c = 0; c < NCHUNK; c++) {
        uint2* Acur = (c & 1) ? As1 : As0;
        uint2* Anxt = (c & 1) ? As0 : As1;
        if (c + 1 < NCHUNK) load_a(c + 1);  // LDG overlaps compute

#pragma unroll
        for (int ks = 0; ks < 2; ks++) {
            uint32_t ah[MF][4], al[MF][4];
#pragma unroll
            for (int mf = 0; mf < MF; mf++) {
                int r = wm * WM + mf * 16 + g;
                int e = ks * 8 + t4;
                uint2 v0 = Acur[r * AS2 + e];
                uint2 v1 = Acur[(r + 8) * AS2 + e];
                uint2 v2 = Acur[r * AS2 + e + 4];
                uint2 v3 = Acur[(r + 8) * AS2 + e + 4];
                ah[mf][0] = v0.x; al[mf][0] = v0.y;
                ah[mf][1] = v1.x; al[mf][1] = v1.y;
                ah[mf][2] = v2.x; al[mf][2] = v2.y;
                ah[mf][3] = v3.x; al[mf][3] = v3.y;
            }
            uint32_t bh[NF][2], bl[NF][2];
            const int eb = c * 16 + ks * 8 + t4;
#pragma unroll
            for (int nf = 0; nf < NF; nf++) {
                int n = wn * WN + nf * 8 + g;
                uint2 u0 = Bs[n * BS2 + eb];
                uint2 u1 = Bs[n * BS2 + eb + 4];
                bh[nf][0] = u0.x; bl[nf][0] = u0.y;
                bh[nf][1] = u1.x; bl[nf][1] = u1.y;
            }
#pragma unroll
            for (int mf = 0; mf < MF; mf++)
#pragma unroll
                for (int nf = 0; nf < NF; nf++) {
                    mma_f16(acc[mf][nf], ah[mf], bh[nf]);
                    mma_f16(acc[mf][nf], al[mf], bh[nf]);
                    mma_f16(acc[mf][nf], ah[mf], bl[nf]);
                }
        }
        if (c + 1 < NCHUNK) {
            sts_a(Anxt);       // writes other buffer; current readers unaffected
            __syncthreads();
        }
    }

    // ---- store h as fp16 (half2 per pair of columns) ----
#pragma unroll
    for (int mf = 0; mf < MF; mf++) {
#pragma unroll
        for (int nf = 0; nf < NF; nf++) {
            int r0 = rowBase + wm * WM + mf * 16 + g;
            int col = wn * WN + nf * 8 + t4 * 2;
            if (r0 < nrows)
                *(__half2*)(outh + (size_t)r0 * BN + col) =
                    __floats2half2_rn(acc[mf][nf][0], acc[mf][nf][1]);
            if (r0 + 8 < nrows)
                *(__half2*)(outh + (size_t)(r0 + 8) * BN + col) =
                    __floats2half2_rn(acc[mf][nf][2], acc[mf][nf][3]);
        }
    }
}

// ---------------------------------------------------------------------------
// CSR gather aggregation from fp16 h (fp32 accumulate)
// ---------------------------------------------------------------------------
__global__ __launch_bounds__(256)
void gather128(const int* __restrict__ row_start, const int* __restrict__ csr,
               const __half* __restrict__ h, float* __restrict__ agg, int N)
{
    int warp = (blockIdx.x * blockDim.x + threadIdx.x) >> 5;
    int lane = threadIdx.x & 31;
    if (warp >= N) return;
    int start = row_start[warp];
    int end   = row_start[warp + 1];
    float4 acc = make_float4(0.f, 0.f, 0.f, 0.f);
    for (int j = start; j < end; j++) {
        int s0 = __ldg(&csr[j]);
        uint2 raw = *(const uint2*)(h + (size_t)s0 * 128 + lane * 4);
        float2 fa = __half22float2(*(__half2*)&raw.x);
        float2 fb = __half22float2(*(__half2*)&raw.y);
        acc.x += fa.x; acc.y += fa.y; acc.z += fb.x; acc.w += fb.y;
    }
    *(float4*)(agg + (size_t)warp * 128 + lane * 4) = acc;
}

__global__ __launch_bounds__(256)
void gather64(const int* __restrict__ row_start, const int* __restrict__ csr,
              const __half* __restrict__ h, float* __restrict__ agg, int N)
{
    int warp = (blockIdx.x * blockDim.x + threadIdx.x) >> 5;
    int lane = threadIdx.x & 31;
    if (warp >= N) return;
    int start = row_start[warp];
    int end   = row_start[warp + 1];
    float2 acc = make_float2(0.f, 0.f);
    for (int j = start; j < end; j++) {
        int s0 = __ldg(&csr[j]);
        __half2 raw = *(const __half2*)(h + (size_t)s0 * 64 + lane * 2);
        float2 f = __half22float2(raw);
        acc.x += f.x; acc.y += f.y;
    }
    *(float2*)(agg + (size_t)warp * 64 + lane * 2) = acc;
}

// Final-layer gather with fused epilogue: out = lrelu(acc * rs_in + b2)
__global__ __launch_bounds__(256)
void gather64_epi(const int* __restrict__ row_start, const int* __restrict__ csr,
                  const __half* __restrict__ h, const float* __restrict__ rs_in,
                  const float* __restrict__ b, float* __restrict__ out, int N)
{
    int warp = (blockIdx.x * blockDim.x + threadIdx.x) >> 5;
    int lane = threadIdx.x & 31;
    if (warp >= N) return;
    int start = row_start[warp];
    int end   = row_start[warp + 1];
    float2 acc = make_float2(0.f, 0.f);
    for (int j = start; j < end; j++) {
        int s0 = __ldg(&csr[j]);
        __half2 raw = *(const __half2*)(h + (size_t)s0 * 64 + lane * 2);
        float2 f = __half22float2(raw);
        acc.x += f.x; acc.y += f.y;
    }
    float ri = rs_in[warp];
    int c = lane * 2;
    float2 o;
    o.x = lrelu(fmaf(acc.x, ri, b[c + 0]));
    o.y = lrelu(fmaf(acc.y, ri, b[c + 1]));
    *(float2*)(out + (size_t)warp * 64 + c) = o;
}

// ---------------------------------------------------------------------------
// Launch
// ---------------------------------------------------------------------------
static inline int cdiv(int a, int b) { return (a + b - 1) / b; }

extern "C" void kernel_launch(void* const* d_in, const int* in_sizes, int n_in,
                              void* d_out, int out_size)
{
    const float* n_feat = (const float*)d_in[0];
    const int*   src    = (const int*)  d_in[1];
    const int*   dst    = (const int*)  d_in[2];
    const float* W0     = (const float*)d_in[3];
    const float* b0     = (const float*)d_in[4];
    const float* W1     = (const float*)d_in[5];
    const float* b1     = (const float*)d_in[6];
    const float* W2     = (const float*)d_in[7];
    const float* b2     = (const float*)d_in[8];
    float* out = (float*)d_out;

    const int N = in_sizes[0] / 128;
    const int E = in_sizes[1];

    float *d_agg, *d_rso, *d_rsi;
    __half* d_h;
    int *d_indeg, *d_excl, *d_rs, *d_cur, *d_csr, *d_bsum;
    uint2 *d_bt;
    cudaGetSymbolAddress((void**)&d_h,    g_h16);
    cudaGetSymbolAddress((void**)&d_agg,  g_agg);
    cudaGetSymbolAddress((void**)&d_rso,  g_rs_out);
    cudaGetSymbolAddress((void**)&d_rsi,  g_rs_in);
    cudaGetSymbolAddress((void**)&d_indeg, g_indeg);
    cudaGetSymbolAddress((void**)&d_excl, g_excl);
    cudaGetSymbolAddress((void**)&d_rs,   g_row_start);
    cudaGetSymbolAddress((void**)&d_cur,  g_cursor);
    cudaGetSymbolAddress((void**)&d_csr,  g_csr_src);
    cudaGetSymbolAddress((void**)&d_bsum, g_bsum);
    cudaGetSymbolAddress((void**)&d_bt,   g_bt);

    // SMEM: (2*128*AS2 + BN*BS2) * 8 bytes
    constexpr int SMEM_L0 = (2 * 128 * 20 + 128 * 68) * 8;  // 110592
    constexpr int SMEM_L1 = (2 * 128 * 20 + 64 * 68) * 8;   // 75776
    constexpr int SMEM_L2 = (2 * 128 * 20 + 64 * 36) * 8;   // 59392

    static cudaStream_t s2 = nullptr;
    static cudaEvent_t ev0 = nullptr, ev1 = nullptr;
    if (!s2) {
        cudaFuncSetAttribute(gemm_mma<128, 128, true>,
                             cudaFuncAttributeMaxDynamicSharedMemorySize, SMEM_L0);
        cudaFuncSetAttribute(gemm_mma<128, 64, false>,
                             cudaFuncAttributeMaxDynamicSharedMemorySize, SMEM_L1);
        cudaFuncSetAttribute(gemm_mma<64, 64, false>,
                             cudaFuncAttributeMaxDynamicSharedMemorySize, SMEM_L2);
        cudaStreamCreateWithFlags(&s2, cudaStreamNonBlocking);
        cudaEventCreateWithFlags(&ev0, cudaEventDisableTiming);
        cudaEventCreateWithFlags(&ev1, cudaEventDisableTiming);
    }

    const int gemm_blocks = cdiv(N, 128);
    const int gw_blocks = cdiv(N, 8);
    const int nb = cdiv(N, 1024);

    // ---- main stream head (launches 1-6; #6 = gemm0 for ncu -s 5) ----
    cudaMemsetAsync(d_indeg, 0, (size_t)N * sizeof(int));                      // 1
    cudaMemsetAsync(d_rso, 0, (size_t)N * sizeof(float));                      // 2
    deg_kernel<<<cdiv(E, 256), 256>>>(src, dst, d_rso, d_indeg, E);            // 3
    cudaEventRecord(ev0, 0);  // fork point: indeg ready
    rsqrt_kernel<<<cdiv(N, 256), 256>>>(d_rso, d_indeg, d_rsi, N);             // 4
    split_w<<<cdiv(128 * 64, 256), 256>>>(W0, d_bt, 128, 128);                 // 5
    gemm_mma<128, 128, true><<<gemm_blocks, 256, SMEM_L0>>>(                   // 6
        n_feat, d_bt, nullptr, d_rso, d_rsi, d_h, N);

    // ---- s2: CSR chain, concurrent with rsqrt/split_w/gemm0 ----
    cudaStreamWaitEvent(s2, ev0, 0);
    scan_block<<<nb, 256, 0, s2>>>(d_indeg, d_excl, d_bsum, N);
    scan_bsum<<<1, 512, 0, s2>>>(d_bsum, nb);
    scan_add<<<cdiv(N, 256), 256, 0, s2>>>(d_excl, d_bsum, d_rs, d_cur, N, E);
    fill_csr<<<cdiv(E, 256), 256, 0, s2>>>(src, dst, d_cur, d_csr, E);
    cudaEventRecord(ev1, s2);

    // ---- join: gathers need the CSR ----
    cudaStreamWaitEvent(0, ev1, 0);
    gather128<<<gw_blocks, 256>>>(d_rs, d_csr, d_h, d_agg, N);

    // --- layer 1: 128 -> 64 ---
    split_w<<<cdiv(64 * 64, 256), 256>>>(W1, d_bt, 128, 64);
    gemm_mma<128, 64, false><<<gemm_blocks, 256, SMEM_L1>>>(
        d_agg, d_bt, b0, d_rso, d_rsi, d_h, N);
    gather64<<<gw_blocks, 256>>>(d_rs, d_csr, d_h, d_agg, N);

    // --- layer 2: 64 -> 64 ---
    split_w<<<cdiv(64 * 32, 256), 256>>>(W2, d_bt, 64, 64);
    gemm_mma<64, 64, false><<<gemm_blocks, 256, SMEM_L2>>>(
        d_agg, d_bt, b1, d_rso, d_rsi, d_h, N);
    gather64_epi<<<gw_blocks, 256>>>(d_rs, d_csr, d_h, d_rsi, b2, out, N);
}

// round 9
// speedup vs baseline: 1.4501x; 1.1170x over previous
#include <cuda_runtime.h>
#include <cuda_bf16.h>
#include <cuda_fp16.h>
#include <cstdint>

#define LEAKY 0.01f

static constexpr int MAX_N = 100000;
static constexpr int MAX_E = 1600000;

// Scratch (module-scope device globals; allocation inside kernel_launch is forbidden)
__device__ __half   g_h16[(size_t)MAX_N * 128];  // GEMM output (fp16) / gather source
__device__ float    g_agg[(size_t)MAX_N * 128];  // gather destination (fp32) / next GEMM input
__device__ float    g_rs_out[MAX_N];             // rsqrt(max(out_deg,1))
__device__ float    g_rs_in[MAX_N];              // rsqrt(max(in_deg,1))
__device__ int      g_indeg[MAX_N];              // int in-degree counts
__device__ int      g_excl[MAX_N];               // scan scratch
__device__ int      g_row_start[MAX_N + 1];      // CSR row offsets (by dst)
__device__ int      g_cursor[MAX_N];             // CSR fill cursors
__device__ int      g_csr_src[MAX_E];            // CSR column (src node) array
__device__ int      g_bsum[512];                 // scan block sums
__device__ uint32_t g_bth[128 * 64];             // W^T fp16-hi half2 [n][k/2]

__device__ __forceinline__ float lrelu(float t) {
    return (t >= 0.f) ? t : LEAKY * t;
}

__device__ __forceinline__ uint32_t h2bits(__half2 h) {
    return *reinterpret_cast<uint32_t*>(&h);
}

// split two floats into fp16 hi/lo planes packed as half2 words
__device__ __forceinline__ uint2 split2(float a, float b) {
    __half2 h = __floats2half2_rn(a, b);
    float la = a - __low2float(h);
    float lb = b - __high2float(h);
    __half2 l = __floats2half2_rn(la, lb);
    return make_uint2(h2bits(h), h2bits(l));
}

__device__ __forceinline__ void mma_f16(float* d, const uint32_t* a, const uint32_t* b) {
    asm volatile(
        "mma.sync.aligned.m16n8k16.row.col.f32.f16.f16.f32 "
        "{%0,%1,%2,%3}, {%4,%5,%6,%7}, {%8,%9}, {%0,%1,%2,%3};"
        : "+f"(d[0]), "+f"(d[1]), "+f"(d[2]), "+f"(d[3])
        : "r"(a[0]), "r"(a[1]), "r"(a[2]), "r"(a[3]), "r"(b[0]), "r"(b[1]));
}

// ---------------------------------------------------------------------------
// Degrees: single E pass, both atomics
// ---------------------------------------------------------------------------
__global__ void deg_kernel(const int* __restrict__ src, const int* __restrict__ dst,
                           float* __restrict__ dout, int* __restrict__ indeg, int E) {
    int i = blockIdx.x * blockDim.x + threadIdx.x;
    if (i < E) {
        atomicAdd(&dout[src[i]], 1.0f);
        atomicAdd(&indeg[dst[i]], 1);
    }
}

__global__ void rsqrt_kernel(float* __restrict__ dout, const int* __restrict__ indeg,
                             float* __restrict__ rsin, int N) {
    int i = blockIdx.x * blockDim.x + threadIdx.x;
    if (i < N) {
        dout[i] = rsqrtf(fmaxf(dout[i], 1.0f));
        rsin[i] = rsqrtf(fmaxf((float)indeg[i], 1.0f));
    }
}

// ---------------------------------------------------------------------------
// Exclusive scan over in-degrees
// ---------------------------------------------------------------------------
__global__ void scan_block(const int* __restrict__ deg, int* __restrict__ excl,
                           int* __restrict__ bsum, int N) {
    __shared__ int ts[256];
    int tid = threadIdx.x;
    int base = blockIdx.x * 1024 + tid * 4;
    int v[4];
    int sum = 0;
#pragma unroll
    for (int i = 0; i < 4; i++) {
        int idx = base + i;
        v[i] = (idx < N) ? deg[idx] : 0;
        sum += v[i];
    }
    ts[tid] = sum;
    __syncthreads();
    for (int off = 1; off < 256; off <<= 1) {
        int t = (tid >= off) ? ts[tid - off] : 0;
        __syncthreads();
        ts[tid] += t;
        __syncthreads();
    }
    if (tid == 255) bsum[blockIdx.x] = ts[255];
    int run = ts[tid] - sum;
#pragma unroll
    for (int i = 0; i < 4; i++) {
        int idx = base + i;
        if (idx < N) excl[idx] = run;
        run += v[i];
    }
}

__global__ void scan_bsum(int* __restrict__ bsum, int nb) {
    __shared__ int s[512];
    int tid = threadIdx.x;
    int v = (tid < nb) ? bsum[tid] : 0;
    s[tid] = v;
    __syncthreads();
    for (int off = 1; off < 512; off <<= 1) {
        int t = (tid >= off) ? s[tid - off] : 0;
        __syncthreads();
        s[tid] += t;
        __syncthreads();
    }
    if (tid < nb) bsum[tid] = s[tid] - v;
}

__global__ void scan_add(const int* __restrict__ excl, const int* __restrict__ bsum,
                         int* __restrict__ row_start, int* __restrict__ cursor,
                         int N, int E) {
    int i = blockIdx.x * blockDim.x + threadIdx.x;
    if (i < N) {
        int v = excl[i] + bsum[i >> 10];
        row_start[i] = v;
        cursor[i] = v;
    }
    if (i == 0) row_start[N] = E;
}

__global__ void fill_csr(const int* __restrict__ src, const int* __restrict__ dst,
                         int* __restrict__ cursor, int* __restrict__ csr_src, int E) {
    int e = blockIdx.x * blockDim.x + threadIdx.x;
    if (e < E) {
        int pos = atomicAdd(&cursor[dst[e]], 1);
        csr_src[pos] = src[e];
    }
}

// ---------------------------------------------------------------------------
// W split: bth[n*(K/2)+j] = fp16-hi half2 of (W[2j][n], W[2j+1][n])
// ---------------------------------------------------------------------------
__global__ void split_w(const float* __restrict__ W, uint32_t* __restrict__ bth, int K, int BN) {
    int idx = blockIdx.x * blockDim.x + threadIdx.x;
    int KP = K >> 1;
    if (idx >= BN * KP) return;
    int n = idx / KP;
    int j = idx % KP;
    float w0 = W[(size_t)(2 * j) * BN + n];
    float w1 = W[(size_t)(2 * j + 1) * BN + n];
    bth[idx] = h2bits(__floats2half2_rn(w0, w1));
}

// ---------------------------------------------------------------------------
// fp16 2-term split GEMM (m16n8k16): outh = fp16( (a_hi+a_lo) @ w_hi )
//   FIRST=true :  pre(a) = a * rs_out[row]
//   FIRST=false:  pre(a) = lrelu(a * rs_in[row] + bprev[k]) * rs_out[row]
// B (hi plane) resident in SMEM; A (hi/lo uint2) double-buffered, BK=32.
// ---------------------------------------------------------------------------
template<int K, int BN, bool FIRST>
__global__ __launch_bounds__(256, 2)
void gemm_mma(const float* __restrict__ A, const uint32_t* __restrict__ Bt,
              const float* __restrict__ bprev,
              const float* __restrict__ rs_out, const float* __restrict__ rs_in,
              __half* __restrict__ outh, int nrows)
{
    constexpr int WARPS_M = (BN == 128) ? 2 : 4;
    constexpr int WM = 128 / WARPS_M;   // 64 or 32
    constexpr int WN = 32;
    constexpr int MF = WM / 16;         // 4 or 2
    constexpr int NF = 4;
    constexpr int KP = K / 2;           // fp16 pairs per row
    constexpr int AS2 = 20;             // A row stride in uint2
    constexpr int BS1 = KP + 4;         // B row stride in uint32 (68 or 36)
    constexpr int NCHUNK = K / 32;

    extern __shared__ __align__(16) uint2 smem2[];
    uint2*    As0 = smem2;                                  // [128][AS2]
    uint2*    As1 = smem2 + 128 * AS2;                      // [128][AS2]
    uint32_t* Bs  = (uint32_t*)(smem2 + 2 * 128 * AS2);     // [BN][BS1]

    const int tid = threadIdx.x;
    const int wid = tid >> 5;
    const int lane = tid & 31;
    const int wm = wid % WARPS_M;
    const int wn = wid / WARPS_M;
    const int rowBase = blockIdx.x * 128;
    const int g = lane >> 2;
    const int t4 = lane & 3;

    // ---- load resident B (hi plane only) ----
    constexpr int BU4 = BN * KP / 4;  // uint4 count
#pragma unroll 4
    for (int idx = tid; idx < BU4; idx += 256) {
        int lin = idx * 4;
        int n = lin / KP;
        int j = lin % KP;
        uint4 v = *(const uint4*)(Bt + (size_t)n * KP + j);
        *(uint4*)(Bs + n * BS1 + j) = v;
    }

    // ---- A chunk staging ----
    float4 q[4];
    int a_r[4], a_kq[4];
#pragma unroll
    for (int i = 0; i < 4; i++) {
        int lin = tid + i * 256;
        a_r[i] = lin >> 3;
        a_kq[i] = lin & 7;
    }

    auto load_a = [&](int c) {
#pragma unroll
        for (int i = 0; i < 4; i++) {
            int row = rowBase + a_r[i];
            float4 v = make_float4(0.f, 0.f, 0.f, 0.f);
            if (row < nrows) {
                v = *(const float4*)(A + (size_t)row * K + c * 32 + a_kq[i] * 4);
                if (FIRST) {
                    float ro = rs_out[row];
                    v.x *= ro; v.y *= ro; v.z *= ro; v.w *= ro;
                } else {
                    float ri = rs_in[row];
                    float ro = rs_out[row];
                    int kk = c * 32 + a_kq[i] * 4;
                    v.x = lrelu(fmaf(v.x, ri, bprev[kk + 0])) * ro;
                    v.y = lrelu(fmaf(v.y, ri, bprev[kk + 1])) * ro;
                    v.z = lrelu(fmaf(v.z, ri, bprev[kk + 2])) * ro;
                    v.w = lrelu(fmaf(v.w, ri, bprev[kk + 3])) * ro;
                }
            }
            q[i] = v;
        }
    };
    auto sts_a = [&](uint2* buf) {
#pragma unroll
        for (int i = 0; i < 4; i++) {
            uint2 e0 = split2(q[i].x, q[i].y);
            uint2 e1 = split2(q[i].z, q[i].w);
            uint4 st = make_uint4(e0.x, e0.y, e1.x, e1.y);
            *(uint4*)(buf + a_r[i] * AS2 + a_kq[i] * 2) = st;
        }
    };

    load_a(0);
    sts_a(As0);
    __syncthreads();

    float acc[MF][NF][4];
#pragma unroll
    for (int i = 0; i < MF; i++)
#pragma unroll
        for (int j = 0; j < NF; j++)
#pragma unroll
            for (int c = 0; c < 4; c++) acc[i][j][c] = 0.f;

#pragma unroll
    for (int c = 0; c < NCHUNK; c++) {
        uint2* Acur = (c & 1) ? As1 : As0;
        uint2* Anxt = (c & 1) ? As0 : As1;
        if (c + 1 < NCHUNK) load_a(c + 1);  // LDG overlaps compute

#pragma unroll
        for (int ks = 0; ks < 2; ks++) {
            uint32_t ah[MF][4], al[MF][4];
#pragma unroll
            for (int mf = 0; mf < MF; mf++) {
                int r = wm * WM + mf * 16 + g;
                int e = ks * 8 + t4;
                uint2 v0 = Acur[r * AS2 + e];
                uint2 v1 = Acur[(r + 8) * AS2 + e];
                uint2 v2 = Acur[r * AS2 + e + 4];
                uint2 v3 = Acur[(r + 8) * AS2 + e + 4];
                ah[mf][0] = v0.x; al[mf][0] = v0.y;
                ah[mf][1] = v1.x; al[mf][1] = v1.y;
                ah[mf][2] = v2.x; al[mf][2] = v2.y;
                ah[mf][3] = v3.x; al[mf][3] = v3.y;
            }
            uint32_t bh[NF][2];
            const int eb = c * 16 + ks * 8 + t4;
#pragma unroll
            for (int nf = 0; nf < NF; nf++) {
                int n = wn * WN + nf * 8 + g;
                bh[nf][0] = Bs[n * BS1 + eb];
                bh[nf][1] = Bs[n * BS1 + eb + 4];
            }
#pragma unroll
            for (int mf = 0; mf < MF; mf++)
#pragma unroll
                for (int nf = 0; nf < NF; nf++) {
                    mma_f16(acc[mf][nf], ah[mf], bh[nf]);
                    mma_f16(acc[mf][nf], al[mf], bh[nf]);
                }
        }
        if (c + 1 < NCHUNK) {
            sts_a(Anxt);
            __syncthreads();
        }
    }

    // ---- store h as fp16 ----
#pragma unroll
    for (int mf = 0; mf < MF; mf++) {
#pragma unroll
        for (int nf = 0; nf < NF; nf++) {
            int r0 = rowBase + wm * WM + mf * 16 + g;
            int col = wn * WN + nf * 8 + t4 * 2;
            if (r0 < nrows)
                *(__half2*)(outh + (size_t)r0 * BN + col) =
                    __floats2half2_rn(acc[mf][nf][0], acc[mf][nf][1]);
            if (r0 + 8 < nrows)
                *(__half2*)(outh + (size_t)(r0 + 8) * BN + col) =
                    __floats2half2_rn(acc[mf][nf][2], acc[mf][nf][3]);
        }
    }
}

// ---------------------------------------------------------------------------
// CSR gather aggregation from fp16 h (fp32 accumulate)
// ---------------------------------------------------------------------------
__global__ __launch_bounds__(256)
void gather128(const int* __restrict__ row_start, const int* __restrict__ csr,
               const __half* __restrict__ h, float* __restrict__ agg, int N)
{
    int warp = (blockIdx.x * blockDim.x + threadIdx.x) >> 5;
    int lane = threadIdx.x & 31;
    if (warp >= N) return;
    int start = row_start[warp];
    int end   = row_start[warp + 1];
    float4 acc = make_float4(0.f, 0.f, 0.f, 0.f);
    for (int j = start; j < end; j++) {
        int s0 = __ldg(&csr[j]);
        uint2 raw = *(const uint2*)(h + (size_t)s0 * 128 + lane * 4);
        float2 fa = __half22float2(*(__half2*)&raw.x);
        float2 fb = __half22float2(*(__half2*)&raw.y);
        acc.x += fa.x; acc.y += fa.y; acc.z += fb.x; acc.w += fb.y;
    }
    *(float4*)(agg + (size_t)warp * 128 + lane * 4) = acc;
}

__global__ __launch_bounds__(256)
void gather64(const int* __restrict__ row_start, const int* __restrict__ csr,
              const __half* __restrict__ h, float* __restrict__ agg, int N)
{
    int warp = (blockIdx.x * blockDim.x + threadIdx.x) >> 5;
    int lane = threadIdx.x & 31;
    if (warp >= N) return;
    int start = row_start[warp];
    int end   = row_start[warp + 1];
    float2 acc = make_float2(0.f, 0.f);
    for (int j = start; j < end; j++) {
        int s0 = __ldg(&csr[j]);
        __half2 raw = *(const __half2*)(h + (size_t)s0 * 64 + lane * 2);
        float2 f = __half22float2(raw);
        acc.x += f.x; acc.y += f.y;
    }
    *(float2*)(agg + (size_t)warp * 64 + lane * 2) = acc;
}

// Final-layer gather with fused epilogue: out = lrelu(acc * rs_in + b2)
__global__ __launch_bounds__(256)
void gather64_epi(const int* __restrict__ row_start, const int* __restrict__ csr,
                  const __half* __restrict__ h, const float* __restrict__ rs_in,
                  const float* __restrict__ b, float* __restrict__ out, int N)
{
    int warp = (blockIdx.x * blockDim.x + threadIdx.x) >> 5;
    int lane = threadIdx.x & 31;
    if (warp >= N) return;
    int start = row_start[warp];
    int end   = row_start[warp + 1];
    float2 acc = make_float2(0.f, 0.f);
    for (int j = start; j < end; j++) {
        int s0 = __ldg(&csr[j]);
        __half2 raw = *(const __half2*)(h + (size_t)s0 * 64 + lane * 2);
        float2 f = __half22float2(raw);
        acc.x += f.x; acc.y += f.y;
    }
    float ri = rs_in[warp];
    int c = lane * 2;
    float2 o;
    o.x = lrelu(fmaf(acc.x, ri, b[c + 0]));
    o.y = lrelu(fmaf(acc.y, ri, b[c + 1]));
    *(float2*)(out + (size_t)warp * 64 + c) = o;
}

// ---------------------------------------------------------------------------
// Launch
// ---------------------------------------------------------------------------
static inline int cdiv(int a, int b) { return (a + b - 1) / b; }

extern "C" void kernel_launch(void* const* d_in, const int* in_sizes, int n_in,
                              void* d_out, int out_size)
{
    const float* n_feat = (const float*)d_in[0];
    const int*   src    = (const int*)  d_in[1];
    const int*   dst    = (const int*)  d_in[2];
    const float* W0     = (const float*)d_in[3];
    const float* b0     = (const float*)d_in[4];
    const float* W1     = (const float*)d_in[5];
    const float* b1     = (const float*)d_in[6];
    const float* W2     = (const float*)d_in[7];
    const float* b2     = (const float*)d_in[8];
    float* out = (float*)d_out;

    const int N = in_sizes[0] / 128;
    const int E = in_sizes[1];

    float *d_agg, *d_rso, *d_rsi;
    __half* d_h;
    int *d_indeg, *d_excl, *d_rs, *d_cur, *d_csr, *d_bsum;
    uint32_t *d_bth;
    cudaGetSymbolAddress((void**)&d_h,    g_h16);
    cudaGetSymbolAddress((void**)&d_agg,  g_agg);
    cudaGetSymbolAddress((void**)&d_rso,  g_rs_out);
    cudaGetSymbolAddress((void**)&d_rsi,  g_rs_in);
    cudaGetSymbolAddress((void**)&d_indeg, g_indeg);
    cudaGetSymbolAddress((void**)&d_excl, g_excl);
    cudaGetSymbolAddress((void**)&d_rs,   g_row_start);
    cudaGetSymbolAddress((void**)&d_cur,  g_cursor);
    cudaGetSymbolAddress((void**)&d_csr,  g_csr_src);
    cudaGetSymbolAddress((void**)&d_bsum, g_bsum);
    cudaGetSymbolAddress((void**)&d_bth,  g_bth);

    // SMEM: 2*128*AS2*8 (A db) + BN*BS1*4 (B hi)
    constexpr int SMEM_L0 = 2 * 128 * 20 * 8 + 128 * 68 * 4;  // 75776
    constexpr int SMEM_L1 = 2 * 128 * 20 * 8 + 64 * 68 * 4;   // 58368
    constexpr int SMEM_L2 = 2 * 128 * 20 * 8 + 64 * 36 * 4;   // 50176

    static cudaStream_t s2 = nullptr;
    static cudaEvent_t ev0 = nullptr, ev1 = nullptr;
    if (!s2) {
        cudaFuncSetAttribute(gemm_mma<128, 128, true>,
                             cudaFuncAttributeMaxDynamicSharedMemorySize, SMEM_L0);
        cudaFuncSetAttribute(gemm_mma<128, 64, false>,
                             cudaFuncAttributeMaxDynamicSharedMemorySize, SMEM_L1);
        cudaFuncSetAttribute(gemm_mma<64, 64, false>,
                             cudaFuncAttributeMaxDynamicSharedMemorySize, SMEM_L2);
        cudaStreamCreateWithFlags(&s2, cudaStreamNonBlocking);
        cudaEventCreateWithFlags(&ev0, cudaEventDisableTiming);
        cudaEventCreateWithFlags(&ev1, cudaEventDisableTiming);
    }

    const int gemm_blocks = cdiv(N, 128);
    const int gw_blocks = cdiv(N, 8);
    const int nb = cdiv(N, 1024);

    // ---- main stream head (launches 1-6; #6 = gemm0 for ncu -s 5) ----
    cudaMemsetAsync(d_indeg, 0, (size_t)N * sizeof(int));                      // 1
    cudaMemsetAsync(d_rso, 0, (size_t)N * sizeof(float));                      // 2
    deg_kernel<<<cdiv(E, 256), 256>>>(src, dst, d_rso, d_indeg, E);            // 3
    cudaEventRecord(ev0, 0);  // fork point: indeg ready
    rsqrt_kernel<<<cdiv(N, 256), 256>>>(d_rso, d_indeg, d_rsi, N);             // 4
    split_w<<<cdiv(128 * 64, 256), 256>>>(W0, d_bth, 128, 128);                // 5
    gemm_mma<128, 128, true><<<gemm_blocks, 256, SMEM_L0>>>(                   // 6
        n_feat, d_bth, nullptr, d_rso, d_rsi, d_h, N);

    // ---- s2: CSR chain, concurrent with rsqrt/split_w/gemm0 ----
    cudaStreamWaitEvent(s2, ev0, 0);
    scan_block<<<nb, 256, 0, s2>>>(d_indeg, d_excl, d_bsum, N);
    scan_bsum<<<1, 512, 0, s2>>>(d_bsum, nb);
    scan_add<<<cdiv(N, 256), 256, 0, s2>>>(d_excl, d_bsum, d_rs, d_cur, N, E);
    fill_csr<<<cdiv(E, 256), 256, 0, s2>>>(src, dst, d_cur, d_csr, E);
    cudaEventRecord(ev1, s2);

    // ---- join: gathers need the CSR ----
    cudaStreamWaitEvent(0, ev1, 0);
    gather128<<<gw_blocks, 256>>>(d_rs, d_csr, d_h, d_agg, N);

    // --- layer 1: 128 -> 64 ---
    split_w<<<cdiv(64 * 64, 256), 256>>>(W1, d_bth, 128, 64);
    gemm_mma<128, 64, false><<<gemm_blocks, 256, SMEM_L1>>>(
        d_agg, d_bth, b0, d_rso, d_rsi, d_h, N);
    gather64<<<gw_blocks, 256>>>(d_rs, d_csr, d_h, d_agg, N);

    // --- layer 2: 64 -> 64 ---
    split_w<<<cdiv(64 * 32, 256), 256>>>(W2, d_bth, 64, 64);
    gemm_mma<64, 64, false><<<gemm_blocks, 256, SMEM_L2>>>(
        d_agg, d_bth, b1, d_rso, d_rsi, d_h, N);
    gather64_epi<<<gw_blocks, 256>>>(d_rs, d_csr, d_h, d_rsi, b2, out, N);
}